// round 1
// baseline (speedup 1.0000x reference)
#include <cuda_runtime.h>
#include <math.h>

// Problem constants
#define BS_      4096
#define IN_DIM_  2048
#define NN       16384
#define TOTAL_D_ 129      // 1 (dc) + 64 (pairs) + 64 (slack)
#define KPAD     136      // padded coefficient-dim stride (float4-friendly)
#define K2       132      // gemm2 K loop bound (>=129, 4 chunks of 33)

// Scratch (static device globals -- no dynamic allocation allowed)
__device__ float g_hT[KPAD * BS_];   // [j][b]  transposed h, padded rows zero
__device__ float g_MT[KPAD * NN];    // [j][n]  transposed basis, padded rows zero

// ---------------------------------------------------------------------------
// Basis: M[n,0] = 1/sqrt(N);  M[n,2k-1] = sqrt2/sqrt(N) cos(2pi k n/N);
//        M[n,2k]   = sqrt2/sqrt(N) sin(2pi k n/N);  M[n,65+s] = Ws[n,s].
// Phase reduced exactly via m = (k*n) & (N-1).
// ---------------------------------------------------------------------------
__global__ void build_basis_kernel(const float* __restrict__ Ws) {
    int n = blockIdx.x * blockDim.x + threadIdx.x;
    if (n >= NN) return;
    const float inv = 0.0078125f;                    // 1/128 = 1/sqrt(N)
    const float s2i = 1.41421356237309515f * 0.0078125f;
    const float w   = 6.28318530717958647692f / (float)NN;
    g_MT[n] = inv;
#pragma unroll
    for (int k = 1; k <= 32; k++) {
        int   m  = (k * n) & (NN - 1);
        float th = (float)m * w;
        float s, c;
        sincosf(th, &s, &c);
        g_MT[(2 * k - 1) * NN + n] = s2i * c;
        g_MT[(2 * k    ) * NN + n] = s2i * s;
    }
#pragma unroll
    for (int s = 0; s < 64; s++)
        g_MT[(65 + s) * NN + n] = Ws[n * 64 + s];
#pragma unroll
    for (int j = TOTAL_D_; j < KPAD; j++)
        g_MT[j * NN + n] = 0.0f;
}

// h init: bias broadcast (gemm1 accumulates on top via atomics), pad rows zero
__global__ void h_init_kernel(const float* __restrict__ b_proj) {
    int idx = blockIdx.x * blockDim.x + threadIdx.x;
    int stride = gridDim.x * blockDim.x;
    for (; idx < KPAD * BS_; idx += stride) {
        int j = idx / BS_;
        g_hT[idx] = (j < TOTAL_D_) ? b_proj[j] : 0.0f;
    }
}

// ---------------------------------------------------------------------------
// GEMM1: hT[j][b] += sum_k x[b][k] * W[j][k]
// grid = (32 row tiles of 128, 8 K segments of 256). Split-K + atomicAdd.
// Block tile: 128 rows x 144 cols (cols >= 136 padded; >=129 are zero via W guard)
// 256 threads: ty=tid/16 -> 8 rows each, tx=tid%16 -> 9 cols each.
// ---------------------------------------------------------------------------
#define G1_KC   32
#define G1_COLS 144
__global__ __launch_bounds__(256, 2)
void gemm1_kernel(const float* __restrict__ x, const float* __restrict__ W) {
    __shared__ float As[G1_KC][128];      // [k][row]
    __shared__ float Bs[G1_KC][G1_COLS];  // [k][col]

    const int rowBase = blockIdx.x * 128;
    const int kSeg    = blockIdx.y * 256;
    const int tid = threadIdx.x;
    const int ty  = tid >> 4;   // 0..15
    const int tx  = tid & 15;   // 0..15

    float acc[8][9];
#pragma unroll
    for (int i = 0; i < 8; i++)
#pragma unroll
        for (int j = 0; j < 9; j++) acc[i][j] = 0.0f;

    for (int kc = 0; kc < 256; kc += G1_KC) {
        const int kBase = kSeg + kc;
        // Load x tile: 128 rows x 8 float4 along k (coalesced), transpose into As
#pragma unroll
        for (int idx = tid; idx < 1024; idx += 256) {
            int r = idx >> 3, kq = idx & 7;
            float4 v = *(const float4*)&x[(size_t)(rowBase + r) * IN_DIM_ + kBase + 4 * kq];
            As[4 * kq + 0][r] = v.x; As[4 * kq + 1][r] = v.y;
            As[4 * kq + 2][r] = v.z; As[4 * kq + 3][r] = v.w;
        }
        // Load W tile: 144 "rows" x 8 float4 (j >= 129 -> zeros)
        for (int idx = tid; idx < 1152; idx += 256) {
            int j = idx >> 3, kq = idx & 7;
            float4 v = make_float4(0.f, 0.f, 0.f, 0.f);
            if (j < TOTAL_D_)
                v = *(const float4*)&W[(size_t)j * IN_DIM_ + kBase + 4 * kq];
            Bs[4 * kq + 0][j] = v.x; Bs[4 * kq + 1][j] = v.y;
            Bs[4 * kq + 2][j] = v.z; Bs[4 * kq + 3][j] = v.w;
        }
        __syncthreads();
#pragma unroll
        for (int kk = 0; kk < G1_KC; kk++) {
            float a[8], b[9];
            *(float4*)&a[0] = *(const float4*)&As[kk][ty * 8];
            *(float4*)&a[4] = *(const float4*)&As[kk][ty * 8 + 4];
#pragma unroll
            for (int j = 0; j < 9; j++) b[j] = Bs[kk][tx * 9 + j];
#pragma unroll
            for (int i = 0; i < 8; i++)
#pragma unroll
                for (int j = 0; j < 9; j++)
                    acc[i][j] = fmaf(a[i], b[j], acc[i][j]);
        }
        __syncthreads();
    }

#pragma unroll
    for (int i = 0; i < 8; i++)
#pragma unroll
        for (int j = 0; j < 9; j++) {
            int col = tx * 9 + j;
            if (col < KPAD)
                atomicAdd(&g_hT[(size_t)col * BS_ + rowBase + ty * 8 + i], acc[i][j]);
        }
}

// ---------------------------------------------------------------------------
// GEMM2: out[b][n] = sum_{j<132} hT[j][b] * MT[j][n]
// grid = (128 n-tiles, 32 b-tiles); block tile 128x128, 8x8 per thread.
// hT/MT are K-major -> all smem loads are coalesced float4, no transposes.
// ---------------------------------------------------------------------------
#define G2_KC 33
__global__ __launch_bounds__(256, 2)
void gemm2_kernel(float* __restrict__ out) {
    __shared__ float As[G2_KC][128];   // [k][row=batch]
    __shared__ float Bs[G2_KC][128];   // [k][col=n]

    const int colBase = blockIdx.x * 128;
    const int rowBase = blockIdx.y * 128;
    const int tid = threadIdx.x;
    const int ty  = tid >> 4;   // 0..15 -> 8 batch rows
    const int tx  = tid & 15;   // 0..15 -> 8 n cols

    float acc[8][8];
#pragma unroll
    for (int i = 0; i < 8; i++)
#pragma unroll
        for (int j = 0; j < 8; j++) acc[i][j] = 0.0f;

    for (int kBase = 0; kBase < K2; kBase += G2_KC) {
        // 33 k-rows x 32 float4 = 1056 float4 per tile, both coalesced
#pragma unroll
        for (int idx = tid; idx < 1056; idx += 256) {
            int kk = idx >> 5, r4 = idx & 31;
            *(float4*)&As[kk][4 * r4] =
                *(const float4*)&g_hT[(size_t)(kBase + kk) * BS_ + rowBase + 4 * r4];
        }
#pragma unroll
        for (int idx = tid; idx < 1056; idx += 256) {
            int kk = idx >> 5, c4 = idx & 31;
            *(float4*)&Bs[kk][4 * c4] =
                *(const float4*)&g_MT[(size_t)(kBase + kk) * NN + colBase + 4 * c4];
        }
        __syncthreads();
#pragma unroll 3
        for (int kk = 0; kk < G2_KC; kk++) {
            float a[8], b[8];
            *(float4*)&a[0] = *(const float4*)&As[kk][ty * 8];
            *(float4*)&a[4] = *(const float4*)&As[kk][ty * 8 + 4];
            *(float4*)&b[0] = *(const float4*)&Bs[kk][tx * 8];
            *(float4*)&b[4] = *(const float4*)&Bs[kk][tx * 8 + 4];
#pragma unroll
            for (int i = 0; i < 8; i++)
#pragma unroll
                for (int j = 0; j < 8; j++)
                    acc[i][j] = fmaf(a[i], b[j], acc[i][j]);
        }
        __syncthreads();
    }

#pragma unroll
    for (int i = 0; i < 8; i++) {
        size_t base = (size_t)(rowBase + ty * 8 + i) * NN + colBase + tx * 8;
        *(float4*)&out[base]     = make_float4(acc[i][0], acc[i][1], acc[i][2], acc[i][3]);
        *(float4*)&out[base + 4] = make_float4(acc[i][4], acc[i][5], acc[i][6], acc[i][7]);
    }
}

// ---------------------------------------------------------------------------
extern "C" void kernel_launch(void* const* d_in, const int* in_sizes, int n_in,
                              void* d_out, int out_size) {
    const float* x      = (const float*)d_in[0];   // [4096, 2048]
    const float* W_proj = (const float*)d_in[1];   // [129, 2048]
    const float* b_proj = (const float*)d_in[2];   // [129]
    const float* Ws     = (const float*)d_in[3];   // [16384, 64]
    float* out = (float*)d_out;                    // [4096, 16384]

    build_basis_kernel<<<NN / 256, 256>>>(Ws);
    h_init_kernel<<<544, 256>>>(b_proj);

    dim3 g1(BS_ / 128, IN_DIM_ / 256);             // (32, 8) split-K
    gemm1_kernel<<<g1, 256>>>(x, W_proj);

    dim3 g2(NN / 128, BS_ / 128);                  // (128, 32)
    gemm2_kernel<<<g2, 256>>>(out);
}

// round 2
// speedup vs baseline: 2.2593x; 2.2593x over previous
#include <cuda_runtime.h>
#include <math.h>

// Problem constants
#define BS_      4096
#define IN_DIM_  2048
#define NN       16384
#define TOTAL_D_ 129      // 1 (dc) + 64 (pairs) + 64 (slack)
#define KPAD     136      // padded coefficient dim (multiple of 8)

// Scratch (static device globals -- no dynamic allocation allowed)
__device__ float g_hT[KPAD * BS_];    // [j][b] tf32-rounded h (col 0 zeroed)
__device__ float g_hacc[KPAD * BS_];  // [j][b] fp32 gemm1 accumulator
__device__ float g_MT[KPAD * NN];     // [j][n] tf32-rounded basis
__device__ float g_dc[BS_];           // exact fp32 h[:,0]

__device__ __forceinline__ float tf32r(float f) {
    unsigned u;
    asm("cvt.rna.tf32.f32 %0, %1;" : "=r"(u) : "f"(f));
    return __uint_as_float(u);
}

__device__ __forceinline__ void mma_tf32(float* c, const unsigned* a, const unsigned* b) {
    asm volatile(
        "mma.sync.aligned.m16n8k8.row.col.f32.tf32.tf32.f32 "
        "{%0,%1,%2,%3}, {%4,%5,%6,%7}, {%8,%9}, {%0,%1,%2,%3};\n"
        : "+f"(c[0]), "+f"(c[1]), "+f"(c[2]), "+f"(c[3])
        : "r"(a[0]), "r"(a[1]), "r"(a[2]), "r"(a[3]), "r"(b[0]), "r"(b[1]));
}

// ---------------------------------------------------------------------------
// Basis (tf32-rounded): M[n,0]=1/128 (unused: hT col0 zero);
// M[n,2k-1]=sqrt2/128 cos(2pi k n/N); M[n,2k]=sqrt2/128 sin(...);
// M[n,65+s]=Ws[n,s]; rows 129..135 zero.
// ---------------------------------------------------------------------------
__global__ void build_basis_kernel(const float* __restrict__ Ws) {
    int n = blockIdx.x * blockDim.x + threadIdx.x;
    if (n >= NN) return;
    const float s2i = 1.41421356237309515f * 0.0078125f;
    const float w   = 6.28318530717958647692f / (float)NN;
    g_MT[n] = 0.0078125f;
#pragma unroll
    for (int k = 1; k <= 32; k++) {
        int   m  = (k * n) & (NN - 1);
        float th = (float)m * w;
        float s, c;
        sincosf(th, &s, &c);
        g_MT[(2 * k - 1) * NN + n] = tf32r(s2i * c);
        g_MT[(2 * k    ) * NN + n] = tf32r(s2i * s);
    }
#pragma unroll
    for (int s = 0; s < 64; s++)
        g_MT[(65 + s) * NN + n] = tf32r(Ws[n * 64 + s]);
#pragma unroll
    for (int j = TOTAL_D_; j < KPAD; j++)
        g_MT[j * NN + n] = 0.0f;
}

__global__ void zero_hacc_kernel() {
    int idx = blockIdx.x * blockDim.x + threadIdx.x;
    int stride = gridDim.x * blockDim.x;
    for (; idx < KPAD * BS_; idx += stride) g_hacc[idx] = 0.0f;
}

// ---------------------------------------------------------------------------
// GEMM1 (tf32 MMA): hacc[j][b] += sum_k x[b][k] * W[j][k]
// grid (32 m-tiles of 128, 8 k-segments of 256); block 256 (8 warps).
// Warp layout: 4(m) x 2(n); warp tile 32 x 72 -> 2 x 9 mma frags.
// ---------------------------------------------------------------------------
#define G1KC 16
__global__ __launch_bounds__(256, 2)
void gemm1_mma_kernel(const float* __restrict__ x, const float* __restrict__ W) {
    __shared__ float As[G1KC][136];  // [k][m]
    __shared__ float Bs[G1KC][152];  // [k][j]  (stride 152 -> conflict-free frags)

    const int rowBase = blockIdx.x * 128;
    const int kSeg    = blockIdx.y * 256;
    const int tid  = threadIdx.x;
    const int warp = tid >> 5, lane = tid & 31;
    const int wM = warp & 3, wN = warp >> 2;
    const int m0 = wM * 32, n0 = wN * 72;
    const int g = lane >> 2, t = lane & 3;

    float acc[2][9][4];
#pragma unroll
    for (int mi = 0; mi < 2; mi++)
#pragma unroll
        for (int ni = 0; ni < 9; ni++)
#pragma unroll
            for (int q = 0; q < 4; q++) acc[mi][ni][q] = 0.0f;

    for (int kc = 0; kc < 256; kc += G1KC) {
        const int kBase = kSeg + kc;
        // x tile: 128 rows x 16 k (coalesced float4), transpose to As[k][m]
#pragma unroll
        for (int i = tid; i < 512; i += 256) {
            int r = i >> 2, q = (i & 3) << 2;
            float4 v = *(const float4*)&x[(size_t)(rowBase + r) * IN_DIM_ + kBase + q];
            As[q + 0][r] = tf32r(v.x); As[q + 1][r] = tf32r(v.y);
            As[q + 2][r] = tf32r(v.z); As[q + 3][r] = tf32r(v.w);
        }
        // W tile: 144 rows x 16 k (j >= 129 -> zero), transpose to Bs[k][j]
        for (int i = tid; i < 576; i += 256) {
            int j = i >> 2, q = (i & 3) << 2;
            float4 v = make_float4(0.f, 0.f, 0.f, 0.f);
            if (j < TOTAL_D_)
                v = *(const float4*)&W[(size_t)j * IN_DIM_ + kBase + q];
            Bs[q + 0][j] = tf32r(v.x); Bs[q + 1][j] = tf32r(v.y);
            Bs[q + 2][j] = tf32r(v.z); Bs[q + 3][j] = tf32r(v.w);
        }
        __syncthreads();
#pragma unroll
        for (int ks = 0; ks < G1KC; ks += 8) {
            unsigned a[2][4], b[9][2];
#pragma unroll
            for (int mi = 0; mi < 2; mi++) {
                int r = m0 + mi * 16 + g;
                a[mi][0] = __float_as_uint(As[ks + t][r]);
                a[mi][1] = __float_as_uint(As[ks + t][r + 8]);
                a[mi][2] = __float_as_uint(As[ks + t + 4][r]);
                a[mi][3] = __float_as_uint(As[ks + t + 4][r + 8]);
            }
#pragma unroll
            for (int ni = 0; ni < 9; ni++) {
                int c = n0 + ni * 8 + g;
                b[ni][0] = __float_as_uint(Bs[ks + t][c]);
                b[ni][1] = __float_as_uint(Bs[ks + t + 4][c]);
            }
#pragma unroll
            for (int mi = 0; mi < 2; mi++)
#pragma unroll
                for (int ni = 0; ni < 9; ni++)
                    mma_tf32(acc[mi][ni], a[mi], b[ni]);
        }
        __syncthreads();
    }

    // epilogue: split-K accumulate into fp32 hacc[j][b]
#pragma unroll
    for (int mi = 0; mi < 2; mi++) {
        int r = rowBase + m0 + mi * 16 + g;
#pragma unroll
        for (int ni = 0; ni < 9; ni++) {
            int col = n0 + ni * 8 + 2 * t;
            if (col < KPAD) {
                atomicAdd(&g_hacc[(size_t)col * BS_ + r],           acc[mi][ni][0]);
                atomicAdd(&g_hacc[(size_t)(col + 1) * BS_ + r],     acc[mi][ni][1]);
                atomicAdd(&g_hacc[(size_t)col * BS_ + r + 8],       acc[mi][ni][2]);
                atomicAdd(&g_hacc[(size_t)(col + 1) * BS_ + r + 8], acc[mi][ni][3]);
            }
        }
    }
}

// Finalize: add bias; extract exact fp32 DC; tf32-round rest; zero pad rows.
__global__ void finalize_h_kernel(const float* __restrict__ b_proj) {
    int idx = blockIdx.x * blockDim.x + threadIdx.x;
    if (idx >= KPAD * BS_) return;
    int j = idx >> 12;           // /4096
    int b = idx & (BS_ - 1);
    if (j == 0) {
        float v = g_hacc[idx] + b_proj[0];
        g_dc[b] = v;             // exact DC, handled in gemm2 epilogue
        g_hT[idx] = 0.0f;
    } else if (j < TOTAL_D_) {
        g_hT[idx] = tf32r(g_hacc[idx] + b_proj[j]);
    } else {
        g_hT[idx] = 0.0f;
    }
}

// ---------------------------------------------------------------------------
// GEMM2 (tf32 MMA): out[b][n] = sum_{j<136} hT[j][b] * MT[j][n] + dc[b]/128
// grid (128 n-tiles, 32 b-tiles); block tile 128x128; 8 warps 2(m) x 4(n),
// warp tile 64x32 -> 4 x 4 mma frags. Software-pipelined global loads.
// ---------------------------------------------------------------------------
#define KC2 8
__global__ __launch_bounds__(256, 2)
void gemm2_mma_kernel(float* __restrict__ out) {
    __shared__ float As[KC2][136];   // [k][b]
    __shared__ float Bs[KC2][136];   // [k][n]

    const int colBase = blockIdx.x * 128;
    const int rowBase = blockIdx.y * 128;
    const int tid  = threadIdx.x;
    const int warp = tid >> 5, lane = tid & 31;
    const int wM = warp >> 2, wN = warp & 3;
    const int m0 = wM * 64, n0 = wN * 32;
    const int g = lane >> 2, t = lane & 3;

    float acc[4][4][4];
#pragma unroll
    for (int mi = 0; mi < 4; mi++)
#pragma unroll
        for (int ni = 0; ni < 4; ni++)
#pragma unroll
            for (int q = 0; q < 4; q++) acc[mi][ni][q] = 0.0f;

    const int kk = tid >> 5;             // 0..7 (k-row this thread loads)
    const int c4 = (tid & 31) << 2;      // 0..124

    float4 ra = *(const float4*)&g_hT[(size_t)kk * BS_ + rowBase + c4];
    float4 rb = *(const float4*)&g_MT[(size_t)kk * NN + colBase + c4];

    for (int kb = 0; kb < KPAD; kb += KC2) {
        *(float4*)&As[kk][c4] = ra;
        *(float4*)&Bs[kk][c4] = rb;
        __syncthreads();

        float4 na = ra, nb = rb;
        if (kb + KC2 < KPAD) {
            na = *(const float4*)&g_hT[(size_t)(kb + KC2 + kk) * BS_ + rowBase + c4];
            nb = *(const float4*)&g_MT[(size_t)(kb + KC2 + kk) * NN + colBase + c4];
        }

        unsigned a[4][4], b[4][2];
#pragma unroll
        for (int mi = 0; mi < 4; mi++) {
            int r = m0 + mi * 16 + g;
            a[mi][0] = __float_as_uint(As[t][r]);
            a[mi][1] = __float_as_uint(As[t][r + 8]);
            a[mi][2] = __float_as_uint(As[t + 4][r]);
            a[mi][3] = __float_as_uint(As[t + 4][r + 8]);
        }
#pragma unroll
        for (int ni = 0; ni < 4; ni++) {
            int c = n0 + ni * 8 + g;
            b[ni][0] = __float_as_uint(Bs[t][c]);
            b[ni][1] = __float_as_uint(Bs[t + 4][c]);
        }
#pragma unroll
        for (int mi = 0; mi < 4; mi++)
#pragma unroll
            for (int ni = 0; ni < 4; ni++)
                mma_tf32(acc[mi][ni], a[mi], b[ni]);
        __syncthreads();
        ra = na; rb = nb;
    }

    // epilogue: add exact DC term, write float2 pairs
    const float inv = 0.0078125f;   // 1/sqrt(N) = 1/128
#pragma unroll
    for (int mi = 0; mi < 4; mi++) {
        int r = rowBase + m0 + mi * 16 + g;
        float d0 = g_dc[r] * inv;
        float d1 = g_dc[r + 8] * inv;
#pragma unroll
        for (int ni = 0; ni < 4; ni++) {
            int c = colBase + n0 + ni * 8 + 2 * t;
            float2 v0 = make_float2(acc[mi][ni][0] + d0, acc[mi][ni][1] + d0);
            float2 v1 = make_float2(acc[mi][ni][2] + d1, acc[mi][ni][3] + d1);
            *(float2*)&out[(size_t)r * NN + c]       = v0;
            *(float2*)&out[(size_t)(r + 8) * NN + c] = v1;
        }
    }
}

// ---------------------------------------------------------------------------
extern "C" void kernel_launch(void* const* d_in, const int* in_sizes, int n_in,
                              void* d_out, int out_size) {
    const float* x      = (const float*)d_in[0];   // [4096, 2048]
    const float* W_proj = (const float*)d_in[1];   // [129, 2048]
    const float* b_proj = (const float*)d_in[2];   // [129]
    const float* Ws     = (const float*)d_in[3];   // [16384, 64]
    float* out = (float*)d_out;                    // [4096, 16384]

    build_basis_kernel<<<NN / 256, 256>>>(Ws);
    zero_hacc_kernel<<<544, 256>>>();

    dim3 g1(BS_ / 128, IN_DIM_ / 256);             // (32, 8) split-K
    gemm1_mma_kernel<<<g1, 256>>>(x, W_proj);

    finalize_h_kernel<<<(KPAD * BS_ + 255) / 256, 256>>>(b_proj);

    dim3 g2(NN / 128, BS_ / 128);                  // (128, 32)
    gemm2_mma_kernel<<<g2, 256>>>(out);
}

// round 3
// speedup vs baseline: 2.5456x; 1.1267x over previous
#include <cuda_runtime.h>
#include <math.h>

// Problem constants
#define BS_      4096
#define IN_DIM_  2048
#define NN       16384
#define TOTAL_D_ 129      // 1 (dc) + 64 (pairs) + 64 (slack)
#define KPAD     136      // padded coefficient dim (17 chunks of 8)
#define KT       17       // k-chunks of 8

// Scratch (static device globals -- no dynamic allocation allowed)
__device__ float  g_hacc[KPAD * BS_];          // [j][b] fp32 gemm1 accumulator
__device__ float  g_dc[BS_];                   // exact fp32 h[:,0]
// Fragment-shuffled operands for mma.m16n8k8:
//   g_hF[m16][kt][lane] = {a0,a1,a2,a3} for A = h[b][j]
//   g_MF[n16][kt][lane] = {b0(n8lo),b1(n8lo),b0(n8hi),b1(n8hi)} for B = M[n][j]
__device__ float4 g_hF[(BS_ / 16) * KT * 32];  // 2.2 MB
__device__ float4 g_MF[(NN  / 16) * KT * 32];  // 8.9 MB

__device__ __forceinline__ float tf32r(float f) {
    unsigned u;
    asm("cvt.rna.tf32.f32 %0, %1;" : "=r"(u) : "f"(f));
    return __uint_as_float(u);
}

__device__ __forceinline__ void mma_tf32(float* c, const unsigned* a, const unsigned* b) {
    asm volatile(
        "mma.sync.aligned.m16n8k8.row.col.f32.tf32.tf32.f32 "
        "{%0,%1,%2,%3}, {%4,%5,%6,%7}, {%8,%9}, {%0,%1,%2,%3};\n"
        : "+f"(c[0]), "+f"(c[1]), "+f"(c[2]), "+f"(c[3])
        : "r"(a[0]), "r"(a[1]), "r"(a[2]), "r"(a[3]), "r"(b[0]), "r"(b[1]));
}

__device__ __forceinline__ void cp16(void* smem, const void* gptr) {
    unsigned s = (unsigned)__cvta_generic_to_shared(smem);
    asm volatile("cp.async.cg.shared.global [%0], [%1], 16;" :: "r"(s), "l"(gptr));
}
#define CP_COMMIT() asm volatile("cp.async.commit_group;")
#define CP_WAIT(n)  asm volatile("cp.async.wait_group %0;" :: "n"(n))

// ---------------------------------------------------------------------------
// Basis, emitted directly in B-fragment layout.
// M[n,2k-1]=sqrt2/128 cos(2pi k n/N); M[n,2k]=sqrt2/128 sin(...);
// M[n,65+s]=Ws[n,s]; j==0 and j>=129 -> 0 (DC handled exactly in epilogue).
// One warp per (n16, kt) fragment; lane computes its float4.
// ---------------------------------------------------------------------------
__global__ void build_basis_frag_kernel(const float* __restrict__ Ws) {
    int w = (blockIdx.x * blockDim.x + threadIdx.x) >> 5;
    int lane = threadIdx.x & 31;
    if (w >= (NN / 16) * KT) return;
    int n16 = w / KT, kt = w % KT;
    int g = lane >> 2, t = lane & 3;
    const float s2i = 1.41421356237309515f * 0.0078125f;
    const float w0  = 6.28318530717958647692f / (float)NN;
    float v[4];
#pragma unroll
    for (int e = 0; e < 4; e++) {
        int n = n16 * 16 + ((e >> 1) & 1) * 8 + g;
        int j = kt * 8 + t + (e & 1) * 4;
        float val = 0.0f;
        if (j >= 1 && j <= 64) {
            int k = (j + 1) >> 1;
            int m = (k * n) & (NN - 1);
            if (m >= NN / 2) m -= NN;              // theta in [-pi, pi)
            float th = (float)m * w0;
            float s, c;
            __sincosf(th, &s, &c);
            val = tf32r((j & 1) ? s2i * c : s2i * s);
        } else if (j >= 65 && j < TOTAL_D_) {
            val = tf32r(Ws[n * 64 + (j - 65)]);
        }
        v[e] = val;
    }
    g_MF[(size_t)w * 32 + lane] = make_float4(v[0], v[1], v[2], v[3]);
}

__global__ void zero_hacc_kernel() {
    int idx = blockIdx.x * blockDim.x + threadIdx.x;
    int stride = gridDim.x * blockDim.x;
    for (; idx < KPAD * BS_; idx += stride) g_hacc[idx] = 0.0f;
}

// ---------------------------------------------------------------------------
// GEMM1 (tf32 MMA): hacc[j][b] += sum_k x[b][k] * W[j][k]   (split-K, atomics)
// ---------------------------------------------------------------------------
#define G1KC 16
__global__ __launch_bounds__(256, 2)
void gemm1_mma_kernel(const float* __restrict__ x, const float* __restrict__ W) {
    __shared__ float As[G1KC][136];
    __shared__ float Bs[G1KC][152];

    const int rowBase = blockIdx.x * 128;
    const int kSeg    = blockIdx.y * 256;
    const int tid  = threadIdx.x;
    const int warp = tid >> 5, lane = tid & 31;
    const int wM = warp & 3, wN = warp >> 2;
    const int m0 = wM * 32, n0 = wN * 72;
    const int g = lane >> 2, t = lane & 3;

    float acc[2][9][4];
#pragma unroll
    for (int mi = 0; mi < 2; mi++)
#pragma unroll
        for (int ni = 0; ni < 9; ni++)
#pragma unroll
            for (int q = 0; q < 4; q++) acc[mi][ni][q] = 0.0f;

    for (int kc = 0; kc < 256; kc += G1KC) {
        const int kBase = kSeg + kc;
#pragma unroll
        for (int i = tid; i < 512; i += 256) {
            int r = i >> 2, q = (i & 3) << 2;
            float4 v = *(const float4*)&x[(size_t)(rowBase + r) * IN_DIM_ + kBase + q];
            As[q + 0][r] = tf32r(v.x); As[q + 1][r] = tf32r(v.y);
            As[q + 2][r] = tf32r(v.z); As[q + 3][r] = tf32r(v.w);
        }
        for (int i = tid; i < 576; i += 256) {
            int j = i >> 2, q = (i & 3) << 2;
            float4 v = make_float4(0.f, 0.f, 0.f, 0.f);
            if (j < TOTAL_D_)
                v = *(const float4*)&W[(size_t)j * IN_DIM_ + kBase + q];
            Bs[q + 0][j] = tf32r(v.x); Bs[q + 1][j] = tf32r(v.y);
            Bs[q + 2][j] = tf32r(v.z); Bs[q + 3][j] = tf32r(v.w);
        }
        __syncthreads();
#pragma unroll
        for (int ks = 0; ks < G1KC; ks += 8) {
            unsigned a[2][4], b[9][2];
#pragma unroll
            for (int mi = 0; mi < 2; mi++) {
                int r = m0 + mi * 16 + g;
                a[mi][0] = __float_as_uint(As[ks + t][r]);
                a[mi][1] = __float_as_uint(As[ks + t][r + 8]);
                a[mi][2] = __float_as_uint(As[ks + t + 4][r]);
                a[mi][3] = __float_as_uint(As[ks + t + 4][r + 8]);
            }
#pragma unroll
            for (int ni = 0; ni < 9; ni++) {
                int c = n0 + ni * 8 + g;
                b[ni][0] = __float_as_uint(Bs[ks + t][c]);
                b[ni][1] = __float_as_uint(Bs[ks + t + 4][c]);
            }
#pragma unroll
            for (int mi = 0; mi < 2; mi++)
#pragma unroll
                for (int ni = 0; ni < 9; ni++)
                    mma_tf32(acc[mi][ni], a[mi], b[ni]);
        }
        __syncthreads();
    }

#pragma unroll
    for (int mi = 0; mi < 2; mi++) {
        int r = rowBase + m0 + mi * 16 + g;
#pragma unroll
        for (int ni = 0; ni < 9; ni++) {
            int col = n0 + ni * 8 + 2 * t;
            if (col < KPAD) {
                atomicAdd(&g_hacc[(size_t)col * BS_ + r],           acc[mi][ni][0]);
                atomicAdd(&g_hacc[(size_t)(col + 1) * BS_ + r],     acc[mi][ni][1]);
                atomicAdd(&g_hacc[(size_t)col * BS_ + r + 8],       acc[mi][ni][2]);
                atomicAdd(&g_hacc[(size_t)(col + 1) * BS_ + r + 8], acc[mi][ni][3]);
            }
        }
    }
}

// ---------------------------------------------------------------------------
// Finalize h into A-fragment layout: add bias, extract exact DC, tf32-round.
// One warp per (m16, kt) fragment.
// ---------------------------------------------------------------------------
__global__ void finalize_frag_kernel(const float* __restrict__ b_proj) {
    int w = (blockIdx.x * blockDim.x + threadIdx.x) >> 5;
    int lane = threadIdx.x & 31;
    if (w >= (BS_ / 16) * KT) return;
    int m16 = w / KT, kt = w % KT;
    int g = lane >> 2, t = lane & 3;
    float v[4];
#pragma unroll
    for (int e = 0; e < 4; e++) {
        int b = m16 * 16 + (e & 1) * 8 + g;
        int j = kt * 8 + t + (e >> 1) * 4;
        float val = 0.0f;
        if (j == 0) {
            g_dc[b] = g_hacc[b] + b_proj[0];     // exact fp32 DC
        } else if (j < TOTAL_D_) {
            val = tf32r(g_hacc[(size_t)j * BS_ + b] + b_proj[j]);
        }
        v[e] = val;
    }
    g_hF[(size_t)w * 32 + lane] = make_float4(v[0], v[1], v[2], v[3]);
}

// ---------------------------------------------------------------------------
// GEMM2 (tf32 MMA, fragment layout + cp.async pipeline):
//   out[b][n] = sum_j h[b][j] * M[n][j] + dc[b]/128
// Block tile 128(m) x 256(n); 8 warps 2(m) x 4(n); warp tile 64x64.
// 3-stage cp.async pipeline; 8 LDS.128 per warp per 8-k for 32 MMAs.
// ---------------------------------------------------------------------------
#define ST 3
__global__ __launch_bounds__(256, 1)
void gemm2_frag_kernel(float* __restrict__ out) {
    __shared__ float4 As[ST][8][32];    // [stage][m16][lane]
    __shared__ float4 Bs[ST][16][32];   // [stage][n16][lane]

    const int mtile = blockIdx.x;       // 0..31
    const int ntile = blockIdx.y;       // 0..63
    const int tid  = threadIdx.x;
    const int warp = tid >> 5, lane = tid & 31;
    const int wM = warp & 1, wN = warp >> 1;
    const int g = lane >> 2, t = lane & 3;

    const float4* __restrict__ gA = g_hF + (size_t)mtile * 8  * KT * 32;
    const float4* __restrict__ gB = g_MF + (size_t)ntile * 16 * KT * 32;

    const int lm16 = tid >> 5, lln = tid & 31;      // A load coords
    const int ln0 = tid >> 5, ln1 = (tid + 256) >> 5;

    float acc[4][8][4];
#pragma unroll
    for (int mi = 0; mi < 4; mi++)
#pragma unroll
        for (int ni = 0; ni < 8; ni++)
#pragma unroll
            for (int q = 0; q < 4; q++) acc[mi][ni][q] = 0.0f;

    // prologue: stages 0..ST-2
#pragma unroll
    for (int s = 0; s < ST - 1; s++) {
        cp16(&As[s][lm16][lln], gA + ((size_t)lm16 * KT + s) * 32 + lln);
        cp16(&Bs[s][ln0][lln],  gB + ((size_t)ln0  * KT + s) * 32 + lln);
        cp16(&Bs[s][ln1][lln],  gB + ((size_t)ln1  * KT + s) * 32 + lln);
        CP_COMMIT();
    }

    for (int kt = 0; kt < KT; kt++) {
        if (kt + ST - 1 < KT) {
            int st = (kt + ST - 1) % ST, kk = kt + ST - 1;
            cp16(&As[st][lm16][lln], gA + ((size_t)lm16 * KT + kk) * 32 + lln);
            cp16(&Bs[st][ln0][lln],  gB + ((size_t)ln0  * KT + kk) * 32 + lln);
            cp16(&Bs[st][ln1][lln],  gB + ((size_t)ln1  * KT + kk) * 32 + lln);
        }
        CP_COMMIT();
        CP_WAIT(ST - 2);
        __syncthreads();

        const int st = kt % ST;
        float4 af[4], bf[4];
#pragma unroll
        for (int mi = 0; mi < 4; mi++) af[mi] = As[st][wM * 4 + mi][lane];
#pragma unroll
        for (int p = 0; p < 4; p++)    bf[p]  = Bs[st][wN * 4 + p][lane];

#pragma unroll
        for (int mi = 0; mi < 4; mi++) {
            unsigned a[4] = { __float_as_uint(af[mi].x), __float_as_uint(af[mi].y),
                              __float_as_uint(af[mi].z), __float_as_uint(af[mi].w) };
#pragma unroll
            for (int ni = 0; ni < 8; ni++) {
                const float4& q = bf[ni >> 1];
                unsigned b[2];
                if (ni & 1) { b[0] = __float_as_uint(q.z); b[1] = __float_as_uint(q.w); }
                else        { b[0] = __float_as_uint(q.x); b[1] = __float_as_uint(q.y); }
                mma_tf32(acc[mi][ni], a, b);
            }
        }
        __syncthreads();
    }

    // epilogue: add exact DC term, write float2 pairs
    const float inv = 0.0078125f;       // 1/sqrt(N)
    const int rowW = mtile * 128 + wM * 64;
    const int colW = ntile * 256 + wN * 64;
#pragma unroll
    for (int mi = 0; mi < 4; mi++) {
        int r = rowW + mi * 16 + g;
        float d0 = g_dc[r] * inv;
        float d1 = g_dc[r + 8] * inv;
#pragma unroll
        for (int ni = 0; ni < 8; ni++) {
            int c = colW + (ni >> 1) * 16 + (ni & 1) * 8 + 2 * t;
            *(float2*)&out[(size_t)r * NN + c] =
                make_float2(acc[mi][ni][0] + d0, acc[mi][ni][1] + d0);
            *(float2*)&out[(size_t)(r + 8) * NN + c] =
                make_float2(acc[mi][ni][2] + d1, acc[mi][ni][3] + d1);
        }
    }
}

// ---------------------------------------------------------------------------
extern "C" void kernel_launch(void* const* d_in, const int* in_sizes, int n_in,
                              void* d_out, int out_size) {
    const float* x      = (const float*)d_in[0];   // [4096, 2048]
    const float* W_proj = (const float*)d_in[1];   // [129, 2048]
    const float* b_proj = (const float*)d_in[2];   // [129]
    const float* Ws     = (const float*)d_in[3];   // [16384, 64]
    float* out = (float*)d_out;                    // [4096, 16384]

    build_basis_frag_kernel<<<(NN / 16) * KT / 8, 256>>>(Ws);
    zero_hacc_kernel<<<544, 256>>>();

    dim3 g1(BS_ / 128, IN_DIM_ / 256);             // (32, 8) split-K
    gemm1_mma_kernel<<<g1, 256>>>(x, W_proj);

    finalize_frag_kernel<<<(BS_ / 16) * KT / 8, 256>>>(b_proj);

    dim3 g2(BS_ / 128, NN / 256);                  // (32 m, 64 n)
    gemm2_frag_kernel<<<g2, 256>>>(out);
}

// round 4
// speedup vs baseline: 3.1972x; 1.2560x over previous
#include <cuda_runtime.h>
#include <cuda_fp16.h>
#include <math.h>

// Problem constants
#define BS_      4096
#define IN_DIM_  2048
#define NN       16384
#define TOTAL_D_ 129      // 1 (dc) + 64 (pairs) + 64 (slack)
#define KPAD     136      // gemm1 accumulator row count
#define KT16     9        // gemm2 k-chunks of 16 (144 padded)

// Scratch (static device globals -- no dynamic allocation allowed)
__device__ float g_hacc[KPAD * BS_];           // [j][b] fp32 gemm1 accumulator
__device__ float g_dc[BS_];                    // exact fp32 h[:,0]
// fp16 fragment-shuffled operands for mma.m16n8k16:
//  g_hF[m16][kt][lane] = {a0,a1,a2,a3} packed half2   (A = h[b][j])
//  g_MF[n16][kt][lane] = {b0lo,b1lo,b0hi,b1hi}        (B = M[n][j])
__device__ uint4 g_hF[(BS_ / 16) * KT16 * 32]; // 1.2 MB
__device__ uint4 g_MF[(NN  / 16) * KT16 * 32]; // 4.7 MB

__device__ __forceinline__ float tf32r(float f) {
    unsigned u;
    asm("cvt.rna.tf32.f32 %0, %1;" : "=r"(u) : "f"(f));
    return __uint_as_float(u);
}

__device__ __forceinline__ void mma_tf32(float* c, const unsigned* a, const unsigned* b) {
    asm volatile(
        "mma.sync.aligned.m16n8k8.row.col.f32.tf32.tf32.f32 "
        "{%0,%1,%2,%3}, {%4,%5,%6,%7}, {%8,%9}, {%0,%1,%2,%3};\n"
        : "+f"(c[0]), "+f"(c[1]), "+f"(c[2]), "+f"(c[3])
        : "r"(a[0]), "r"(a[1]), "r"(a[2]), "r"(a[3]), "r"(b[0]), "r"(b[1]));
}

__device__ __forceinline__ void mma_f16(float* c, const unsigned* a, const unsigned* b) {
    asm volatile(
        "mma.sync.aligned.m16n8k16.row.col.f32.f16.f16.f32 "
        "{%0,%1,%2,%3}, {%4,%5,%6,%7}, {%8,%9}, {%0,%1,%2,%3};\n"
        : "+f"(c[0]), "+f"(c[1]), "+f"(c[2]), "+f"(c[3])
        : "r"(a[0]), "r"(a[1]), "r"(a[2]), "r"(a[3]), "r"(b[0]), "r"(b[1]));
}

__device__ __forceinline__ void cp16(void* smem, const void* gptr) {
    unsigned s = (unsigned)__cvta_generic_to_shared(smem);
    asm volatile("cp.async.cg.shared.global [%0], [%1], 16;" :: "r"(s), "l"(gptr));
}
#define CP_COMMIT() asm volatile("cp.async.commit_group;")
#define CP_WAIT(n)  asm volatile("cp.async.wait_group %0;" :: "n"(n))

// M[n][j] basis value (DC column j==0 excluded; handled exactly in epilogue)
__device__ __forceinline__ float basis_val(int n, int j, const float* __restrict__ Ws) {
    if (j >= 1 && j <= 64) {
        const float s2i = 1.41421356237309515f * 0.0078125f;
        const float w0  = 6.28318530717958647692f / (float)NN;
        int k = (j + 1) >> 1;
        int m = (k * n) & (NN - 1);
        if (m >= NN / 2) m -= NN;            // theta in [-pi, pi)
        float th = (float)m * w0;
        float s, c;
        __sincosf(th, &s, &c);
        return (j & 1) ? s2i * c : s2i * s;
    }
    if (j >= 65 && j < TOTAL_D_) return Ws[n * 64 + (j - 65)];
    return 0.0f;
}

// ---------------------------------------------------------------------------
// Basis in fp16 B-fragment layout. One warp per (n16, kt) fragment.
// lane(g,t): n = n16*16 + g (+8 hi); j = 16*kt + {2t,2t+1,2t+8,2t+9}.
// ---------------------------------------------------------------------------
__global__ void build_basis_frag_kernel(const float* __restrict__ Ws) {
    int w = (blockIdx.x * blockDim.x + threadIdx.x) >> 5;
    int lane = threadIdx.x & 31;
    if (w >= (NN / 16) * KT16) return;
    int n16 = w / KT16, kt = w % KT16;
    int g = lane >> 2, t = lane & 3;
    int j0 = 16 * kt + 2 * t;
    unsigned r[4];
#pragma unroll
    for (int nsel = 0; nsel < 2; nsel++) {
        int n = n16 * 16 + nsel * 8 + g;
        __half2 lo = __floats2half2_rn(basis_val(n, j0,     Ws), basis_val(n, j0 + 1, Ws));
        __half2 hi = __floats2half2_rn(basis_val(n, j0 + 8, Ws), basis_val(n, j0 + 9, Ws));
        r[2 * nsel]     = *(unsigned*)&lo;
        r[2 * nsel + 1] = *(unsigned*)&hi;
    }
    g_MF[(size_t)w * 32 + lane] = make_uint4(r[0], r[1], r[2], r[3]);
}

__global__ void zero_hacc_kernel() {
    int idx = blockIdx.x * blockDim.x + threadIdx.x;
    int stride = gridDim.x * blockDim.x;
    for (; idx < KPAD * BS_; idx += stride) g_hacc[idx] = 0.0f;
}

// ---------------------------------------------------------------------------
// GEMM1 (tf32 MMA): hacc[j][b] += sum_k x[b][k] * W[j][k]
// grid (32 m-tiles, 16 k-segments of 128) -- 512 blocks for latency hiding.
// ---------------------------------------------------------------------------
#define G1KC 16
__global__ __launch_bounds__(256, 2)
void gemm1_mma_kernel(const float* __restrict__ x, const float* __restrict__ W) {
    __shared__ float As[G1KC][136];
    __shared__ float Bs[G1KC][152];

    const int rowBase = blockIdx.x * 128;
    const int kSeg    = blockIdx.y * 128;
    const int tid  = threadIdx.x;
    const int warp = tid >> 5, lane = tid & 31;
    const int wM = warp & 3, wN = warp >> 2;
    const int m0 = wM * 32, n0 = wN * 72;
    const int g = lane >> 2, t = lane & 3;

    float acc[2][9][4];
#pragma unroll
    for (int mi = 0; mi < 2; mi++)
#pragma unroll
        for (int ni = 0; ni < 9; ni++)
#pragma unroll
            for (int q = 0; q < 4; q++) acc[mi][ni][q] = 0.0f;

    for (int kc = 0; kc < 128; kc += G1KC) {
        const int kBase = kSeg + kc;
#pragma unroll
        for (int i = tid; i < 512; i += 256) {
            int r = i >> 2, q = (i & 3) << 2;
            float4 v = *(const float4*)&x[(size_t)(rowBase + r) * IN_DIM_ + kBase + q];
            As[q + 0][r] = tf32r(v.x); As[q + 1][r] = tf32r(v.y);
            As[q + 2][r] = tf32r(v.z); As[q + 3][r] = tf32r(v.w);
        }
        for (int i = tid; i < 576; i += 256) {
            int j = i >> 2, q = (i & 3) << 2;
            float4 v = make_float4(0.f, 0.f, 0.f, 0.f);
            if (j < TOTAL_D_)
                v = *(const float4*)&W[(size_t)j * IN_DIM_ + kBase + q];
            Bs[q + 0][j] = tf32r(v.x); Bs[q + 1][j] = tf32r(v.y);
            Bs[q + 2][j] = tf32r(v.z); Bs[q + 3][j] = tf32r(v.w);
        }
        __syncthreads();
#pragma unroll
        for (int ks = 0; ks < G1KC; ks += 8) {
            unsigned a[2][4], b[9][2];
#pragma unroll
            for (int mi = 0; mi < 2; mi++) {
                int r = m0 + mi * 16 + g;
                a[mi][0] = __float_as_uint(As[ks + t][r]);
                a[mi][1] = __float_as_uint(As[ks + t][r + 8]);
                a[mi][2] = __float_as_uint(As[ks + t + 4][r]);
                a[mi][3] = __float_as_uint(As[ks + t + 4][r + 8]);
            }
#pragma unroll
            for (int ni = 0; ni < 9; ni++) {
                int c = n0 + ni * 8 + g;
                b[ni][0] = __float_as_uint(Bs[ks + t][c]);
                b[ni][1] = __float_as_uint(Bs[ks + t + 4][c]);
            }
#pragma unroll
            for (int mi = 0; mi < 2; mi++)
#pragma unroll
                for (int ni = 0; ni < 9; ni++)
                    mma_tf32(acc[mi][ni], a[mi], b[ni]);
        }
        __syncthreads();
    }

#pragma unroll
    for (int mi = 0; mi < 2; mi++) {
        int r = rowBase + m0 + mi * 16 + g;
#pragma unroll
        for (int ni = 0; ni < 9; ni++) {
            int col = n0 + ni * 8 + 2 * t;
            if (col < KPAD) {
                atomicAdd(&g_hacc[(size_t)col * BS_ + r],           acc[mi][ni][0]);
                atomicAdd(&g_hacc[(size_t)(col + 1) * BS_ + r],     acc[mi][ni][1]);
                atomicAdd(&g_hacc[(size_t)col * BS_ + r + 8],       acc[mi][ni][2]);
                atomicAdd(&g_hacc[(size_t)(col + 1) * BS_ + r + 8], acc[mi][ni][3]);
            }
        }
    }
}

// ---------------------------------------------------------------------------
// Finalize h into fp16 A-fragments: add bias, extract exact DC.
// One warp per (m16, kt). lane(g,t): b = m16*16+g (+8), j = 16kt+{2t,2t+1,+8,+9}
// ---------------------------------------------------------------------------
__global__ void finalize_frag_kernel(const float* __restrict__ b_proj) {
    int w = (blockIdx.x * blockDim.x + threadIdx.x) >> 5;
    int lane = threadIdx.x & 31;
    if (w >= (BS_ / 16) * KT16) return;
    int m16 = w / KT16, kt = w % KT16;
    int g = lane >> 2, t = lane & 3;
    int j0 = 16 * kt + 2 * t;

    unsigned r[4];
#pragma unroll
    for (int ksel = 0; ksel < 2; ksel++) {       // k-lo pair / k-hi pair
        int ja = j0 + ksel * 8, jb = ja + 1;
#pragma unroll
        for (int rsel = 0; rsel < 2; rsel++) {   // row g / g+8
            int b = m16 * 16 + rsel * 8 + g;
            float va = 0.0f, vb = 0.0f;
            if (ja == 0) {
                g_dc[b] = g_hacc[b] + b_proj[0];          // exact fp32 DC
            } else if (ja < TOTAL_D_) {
                va = g_hacc[(size_t)ja * BS_ + b] + b_proj[ja];
            }
            if (jb < TOTAL_D_)
                vb = g_hacc[(size_t)jb * BS_ + b] + b_proj[jb];
            __half2 p = __floats2half2_rn(va, vb);
            r[ksel * 2 + rsel] = *(unsigned*)&p;          // a0,a1 (klo), a2,a3 (khi)
        }
    }
    g_hF[(size_t)w * 32 + lane] = make_uint4(r[0], r[1], r[2], r[3]);
}

// ---------------------------------------------------------------------------
// GEMM2 (fp16 MMA m16n8k16, fragment layout + cp.async pipeline):
//   out[b][n] = sum_j h[b][j] * M[n][j] + dc[b]/128
// Block 128(m) x 256(n); 8 warps 2(m) x 4(n); warp tile 64x64.
// Per warp per 16-k chunk: 8 LDS.128 feed 32 MMAs.
// ---------------------------------------------------------------------------
#define ST 3
__global__ __launch_bounds__(256, 1)
void gemm2_frag_kernel(float* __restrict__ out) {
    __shared__ uint4 As[ST][8][32];    // [stage][m16][lane]
    __shared__ uint4 Bs[ST][16][32];   // [stage][n16][lane]

    const int mtile = blockIdx.x;      // 0..31
    const int ntile = blockIdx.y;      // 0..63
    const int tid  = threadIdx.x;
    const int warp = tid >> 5, lane = tid & 31;
    const int wM = warp & 1, wN = warp >> 1;
    const int g = lane >> 2, t = lane & 3;

    const uint4* __restrict__ gA = g_hF + (size_t)mtile * 8  * KT16 * 32;
    const uint4* __restrict__ gB = g_MF + (size_t)ntile * 16 * KT16 * 32;

    const int lm16 = tid >> 5, lln = tid & 31;
    const int ln0 = tid >> 5, ln1 = 8 + (tid >> 5);

    float acc[4][8][4];
#pragma unroll
    for (int mi = 0; mi < 4; mi++)
#pragma unroll
        for (int ni = 0; ni < 8; ni++)
#pragma unroll
            for (int q = 0; q < 4; q++) acc[mi][ni][q] = 0.0f;

#pragma unroll
    for (int s = 0; s < ST - 1; s++) {
        cp16(&As[s][lm16][lln], gA + ((size_t)lm16 * KT16 + s) * 32 + lln);
        cp16(&Bs[s][ln0][lln],  gB + ((size_t)ln0  * KT16 + s) * 32 + lln);
        cp16(&Bs[s][ln1][lln],  gB + ((size_t)ln1  * KT16 + s) * 32 + lln);
        CP_COMMIT();
    }

    for (int kt = 0; kt < KT16; kt++) {
        if (kt + ST - 1 < KT16) {
            int st = (kt + ST - 1) % ST, kk = kt + ST - 1;
            cp16(&As[st][lm16][lln], gA + ((size_t)lm16 * KT16 + kk) * 32 + lln);
            cp16(&Bs[st][ln0][lln],  gB + ((size_t)ln0  * KT16 + kk) * 32 + lln);
            cp16(&Bs[st][ln1][lln],  gB + ((size_t)ln1  * KT16 + kk) * 32 + lln);
        }
        CP_COMMIT();
        CP_WAIT(ST - 2);
        __syncthreads();

        const int st = kt % ST;
        uint4 af[4], bf[4];
#pragma unroll
        for (int mi = 0; mi < 4; mi++) af[mi] = As[st][wM * 4 + mi][lane];
#pragma unroll
        for (int p = 0; p < 4; p++)    bf[p]  = Bs[st][wN * 4 + p][lane];

#pragma unroll
        for (int mi = 0; mi < 4; mi++) {
            unsigned a[4] = { af[mi].x, af[mi].y, af[mi].z, af[mi].w };
#pragma unroll
            for (int ni = 0; ni < 8; ni++) {
                const uint4& q = bf[ni >> 1];
                unsigned b[2];
                if (ni & 1) { b[0] = q.z; b[1] = q.w; }
                else        { b[0] = q.x; b[1] = q.y; }
                mma_f16(acc[mi][ni], a, b);
            }
        }
        __syncthreads();
    }

    // epilogue: add exact DC term, write float2 pairs
    const float inv = 0.0078125f;       // 1/sqrt(N)
    const int rowW = mtile * 128 + wM * 64;
    const int colW = ntile * 256 + wN * 64;
#pragma unroll
    for (int mi = 0; mi < 4; mi++) {
        int r = rowW + mi * 16 + g;
        float d0 = g_dc[r] * inv;
        float d1 = g_dc[r + 8] * inv;
#pragma unroll
        for (int ni = 0; ni < 8; ni++) {
            int c = colW + (ni >> 1) * 16 + (ni & 1) * 8 + 2 * t;
            *(float2*)&out[(size_t)r * NN + c] =
                make_float2(acc[mi][ni][0] + d0, acc[mi][ni][1] + d0);
            *(float2*)&out[(size_t)(r + 8) * NN + c] =
                make_float2(acc[mi][ni][2] + d1, acc[mi][ni][3] + d1);
        }
    }
}

// ---------------------------------------------------------------------------
extern "C" void kernel_launch(void* const* d_in, const int* in_sizes, int n_in,
                              void* d_out, int out_size) {
    const float* x      = (const float*)d_in[0];   // [4096, 2048]
    const float* W_proj = (const float*)d_in[1];   // [129, 2048]
    const float* b_proj = (const float*)d_in[2];   // [129]
    const float* Ws     = (const float*)d_in[3];   // [16384, 64]
    float* out = (float*)d_out;                    // [4096, 16384]

    build_basis_frag_kernel<<<(NN / 16) * KT16 / 8, 256>>>(Ws);
    zero_hacc_kernel<<<544, 256>>>();

    dim3 g1(BS_ / 128, IN_DIM_ / 128);             // (32, 16) split-K
    gemm1_mma_kernel<<<g1, 256>>>(x, W_proj);

    finalize_frag_kernel<<<(BS_ / 16) * KT16 / 8, 256>>>(b_proj);

    dim3 g2(BS_ / 128, NN / 256);                  // (32 m, 64 n)
    gemm2_frag_kernel<<<g2, 256>>>(out);
}

// round 6
// speedup vs baseline: 3.5563x; 1.1123x over previous
#include <cuda_runtime.h>
#include <cuda_fp16.h>
#include <math.h>

// Problem constants
#define BS_      4096
#define IN_DIM_  2048
#define NN       16384
#define TOTAL_D_ 129      // 1 (dc) + 64 (pairs) + 64 (slack)
#define KPAD     136      // gemm1 accumulator row count
#define KT16     9        // gemm2 k-chunks of 16 (144 padded)

// Scratch (static device globals -- no dynamic allocation allowed)
__device__ float g_hacc[KPAD * BS_];           // [j][b] fp32 gemm1 accumulator
__device__ float g_dc[BS_];                    // exact fp32 h[:,0]
// fp16 fragment-shuffled operands for mma.m16n8k16:
//  g_hF[m16][kt][lane] = {a0,a1,a2,a3} packed half2   (A = h[b][j])
//  g_MF[n16][kt][lane] = {b0lo,b1lo,b0hi,b1hi}        (B = M[n][j])
__device__ uint4 g_hF[(BS_ / 16) * KT16 * 32]; // 1.2 MB
__device__ uint4 g_MF[(NN  / 16) * KT16 * 32]; // 4.7 MB

__device__ __forceinline__ void mma_f16(float* c, const unsigned* a, const unsigned* b) {
    asm volatile(
        "mma.sync.aligned.m16n8k16.row.col.f32.f16.f16.f32 "
        "{%0,%1,%2,%3}, {%4,%5,%6,%7}, {%8,%9}, {%0,%1,%2,%3};\n"
        : "+f"(c[0]), "+f"(c[1]), "+f"(c[2]), "+f"(c[3])
        : "r"(a[0]), "r"(a[1]), "r"(a[2]), "r"(a[3]), "r"(b[0]), "r"(b[1]));
}

__device__ __forceinline__ void cp16(void* smem, const void* gptr) {
    unsigned s = (unsigned)__cvta_generic_to_shared(smem);
    asm volatile("cp.async.cg.shared.global [%0], [%1], 16;" :: "r"(s), "l"(gptr));
}
#define CP_COMMIT() asm volatile("cp.async.commit_group;")
#define CP_WAIT(n)  asm volatile("cp.async.wait_group %0;" :: "n"(n))

// M[n][j] basis value (DC column j==0 excluded; handled exactly in epilogue)
__device__ __forceinline__ float basis_val(int n, int j, const float* __restrict__ Ws) {
    if (j >= 1 && j <= 64) {
        const float s2i = 1.41421356237309515f * 0.0078125f;
        const float w0  = 6.28318530717958647692f / (float)NN;
        int k = (j + 1) >> 1;
        int m = (k * n) & (NN - 1);
        if (m >= NN / 2) m -= NN;            // theta in [-pi, pi)
        float th = (float)m * w0;
        float s, c;
        __sincosf(th, &s, &c);
        return (j & 1) ? s2i * c : s2i * s;
    }
    if (j >= 65 && j < TOTAL_D_) return Ws[n * 64 + (j - 65)];
    return 0.0f;
}

// ---------------------------------------------------------------------------
// Prep: basis in fp16 B-fragment layout (blocks < 1152) + zero g_hacc (rest).
// Basis: one warp per (n16, kt); lane(g,t): n = n16*16+g (+8); j = 16kt+{2t,..}
// ---------------------------------------------------------------------------
#define BASIS_BLOCKS ((NN / 16) * KT16 / 8)    // 1152
#define ZERO_BLOCKS  (KPAD * BS_ / 4 / 256)    // 544
__global__ void prep_kernel(const float* __restrict__ Ws) {
    if (blockIdx.x < BASIS_BLOCKS) {
        int w = (blockIdx.x * blockDim.x + threadIdx.x) >> 5;
        int lane = threadIdx.x & 31;
        int n16 = w / KT16, kt = w % KT16;
        int g = lane >> 2, t = lane & 3;
        int j0 = 16 * kt + 2 * t;
        unsigned r[4];
#pragma unroll
        for (int nsel = 0; nsel < 2; nsel++) {
            int n = n16 * 16 + nsel * 8 + g;
            __half2 lo = __floats2half2_rn(basis_val(n, j0,     Ws), basis_val(n, j0 + 1, Ws));
            __half2 hi = __floats2half2_rn(basis_val(n, j0 + 8, Ws), basis_val(n, j0 + 9, Ws));
            r[2 * nsel]     = *(unsigned*)&lo;
            r[2 * nsel + 1] = *(unsigned*)&hi;
        }
        g_MF[(size_t)w * 32 + lane] = make_uint4(r[0], r[1], r[2], r[3]);
    } else {
        int idx = (blockIdx.x - BASIS_BLOCKS) * 256 + threadIdx.x;
        ((float4*)g_hacc)[idx] = make_float4(0.f, 0.f, 0.f, 0.f);
    }
}

// ---------------------------------------------------------------------------
// GEMM1 (fp16 MMA m16n8k16): hacc[j][b] += sum_k x[b][k] * W[j][k]
// grid (32 m-tiles, 16 k-segments of 128); K-chunk 16 = one MMA depth.
// ---------------------------------------------------------------------------
__global__ __launch_bounds__(256, 2)
void gemm1_mma_kernel(const float* __restrict__ x, const float* __restrict__ W) {
    __shared__ __half2 Ah[8][136];   // [kpair][m]  (stride 136 words: conflict-free)
    __shared__ __half2 Bh[8][152];   // [kpair][j]  (stride 152 words: conflict-free)

    const int rowBase = blockIdx.x * 128;
    const int kSeg    = blockIdx.y * 128;
    const int tid  = threadIdx.x;
    const int warp = tid >> 5, lane = tid & 31;
    const int wM = warp & 3, wN = warp >> 2;
    const int m0 = wM * 32, n0 = wN * 72;
    const int g = lane >> 2, t = lane & 3;

    float acc[2][9][4];
#pragma unroll
    for (int mi = 0; mi < 2; mi++)
#pragma unroll
        for (int ni = 0; ni < 9; ni++)
#pragma unroll
            for (int q = 0; q < 4; q++) acc[mi][ni][q] = 0.0f;

    for (int kc = 0; kc < 128; kc += 16) {
        const int kBase = kSeg + kc;
        // x tile: 128 rows x 16 k -> Ah[kpair][m]
#pragma unroll
        for (int i = tid; i < 512; i += 256) {
            int r = i >> 2, kp = (i & 3) << 1;   // kp = k-pair index 0,2,4,6
            float4 v = *(const float4*)&x[(size_t)(rowBase + r) * IN_DIM_ + kBase + 2 * kp];
            Ah[kp][r]     = __floats2half2_rn(v.x, v.y);
            Ah[kp + 1][r] = __floats2half2_rn(v.z, v.w);
        }
        // W tile: 144 rows x 16 k (j >= 129 -> zero) -> Bh[kpair][j]
        for (int i = tid; i < 576; i += 256) {
            int j = i >> 2, kp = (i & 3) << 1;
            float4 v = make_float4(0.f, 0.f, 0.f, 0.f);
            if (j < TOTAL_D_)
                v = *(const float4*)&W[(size_t)j * IN_DIM_ + kBase + 2 * kp];
            Bh[kp][j]     = __floats2half2_rn(v.x, v.y);
            Bh[kp + 1][j] = __floats2half2_rn(v.z, v.w);
        }
        __syncthreads();

        unsigned a[2][4], b[9][2];
#pragma unroll
        for (int mi = 0; mi < 2; mi++) {
            int r = m0 + mi * 16 + g;
            a[mi][0] = *(unsigned*)&Ah[t][r];
            a[mi][1] = *(unsigned*)&Ah[t][r + 8];
            a[mi][2] = *(unsigned*)&Ah[t + 4][r];
            a[mi][3] = *(unsigned*)&Ah[t + 4][r + 8];
        }
#pragma unroll
        for (int ni = 0; ni < 9; ni++) {
            int c = n0 + ni * 8 + g;
            b[ni][0] = *(unsigned*)&Bh[t][c];
            b[ni][1] = *(unsigned*)&Bh[t + 4][c];
        }
#pragma unroll
        for (int mi = 0; mi < 2; mi++)
#pragma unroll
            for (int ni = 0; ni < 9; ni++)
                mma_f16(acc[mi][ni], a[mi], b[ni]);
        __syncthreads();
    }

#pragma unroll
    for (int mi = 0; mi < 2; mi++) {
        int r = rowBase + m0 + mi * 16 + g;
#pragma unroll
        for (int ni = 0; ni < 9; ni++) {
            int col = n0 + ni * 8 + 2 * t;
            if (col < KPAD) {
                atomicAdd(&g_hacc[(size_t)col * BS_ + r],           acc[mi][ni][0]);
                atomicAdd(&g_hacc[(size_t)(col + 1) * BS_ + r],     acc[mi][ni][1]);
                atomicAdd(&g_hacc[(size_t)col * BS_ + r + 8],       acc[mi][ni][2]);
                atomicAdd(&g_hacc[(size_t)(col + 1) * BS_ + r + 8], acc[mi][ni][3]);
            }
        }
    }
}

// ---------------------------------------------------------------------------
// Finalize h into fp16 A-fragments: add bias, extract exact DC.
// One warp per (m16, kt). lane(g,t): b = m16*16+g (+8), j = 16kt+{2t,2t+1,+8,+9}
// ---------------------------------------------------------------------------
__global__ void finalize_frag_kernel(const float* __restrict__ b_proj) {
    int w = (blockIdx.x * blockDim.x + threadIdx.x) >> 5;
    int lane = threadIdx.x & 31;
    if (w >= (BS_ / 16) * KT16) return;
    int m16 = w / KT16, kt = w % KT16;
    int g = lane >> 2, t = lane & 3;
    int j0 = 16 * kt + 2 * t;

    unsigned r[4];
#pragma unroll
    for (int ksel = 0; ksel < 2; ksel++) {
        int ja = j0 + ksel * 8, jb = ja + 1;
#pragma unroll
        for (int rsel = 0; rsel < 2; rsel++) {
            int b = m16 * 16 + rsel * 8 + g;
            float va = 0.0f, vb = 0.0f;
            if (ja == 0) {
                g_dc[b] = g_hacc[b] + b_proj[0];          // exact fp32 DC
            } else if (ja < TOTAL_D_) {
                va = g_hacc[(size_t)ja * BS_ + b] + b_proj[ja];
            }
            if (jb < TOTAL_D_)
                vb = g_hacc[(size_t)jb * BS_ + b] + b_proj[jb];
            __half2 p = __floats2half2_rn(va, vb);
            r[ksel * 2 + rsel] = *(unsigned*)&p;
        }
    }
    g_hF[(size_t)w * 32 + lane] = make_uint4(r[0], r[1], r[2], r[3]);
}

// ---------------------------------------------------------------------------
// GEMM2 (fp16 MMA, A resident in smem + B cp.async pipeline):
//   out[b][n] = sum_j h[b][j] * M[n][j] + dc[b]/128
// Block 128(m) x 256(n); 512 threads, 16 warps 2(m) x 8(n); warp tile 64x32.
// Dynamic smem: A frags 36.9KB (loaded once) + B 4-stage ring 32.8KB.
// ---------------------------------------------------------------------------
#define ST 4
#define G2_SMEM ((8 * KT16 * 32 + ST * 16 * 32) * 16)
__global__ __launch_bounds__(512, 1)
void gemm2_frag_kernel(float* __restrict__ out) {
    extern __shared__ uint4 smem[];
    uint4* As = smem;                  // [m16][kt][lane] = [8][9][32]
    uint4* Bs = smem + 8 * KT16 * 32;  // [st][n16][lane] = [ST][16][32]

    const int mtile = blockIdx.x;      // 0..31
    const int ntile = blockIdx.y;      // 0..63
    const int tid  = threadIdx.x;
    const int warp = tid >> 5, lane = tid & 31;
    const int wM = warp >> 3, wN = warp & 7;     // 2(m) x 8(n)
    const int g = lane >> 2, t = lane & 3;

    const uint4* __restrict__ gA = g_hF + (size_t)mtile * 8  * KT16 * 32;
    const uint4* __restrict__ gB = g_MF + (size_t)ntile * 16 * KT16 * 32;

    float acc[4][4][4];
#pragma unroll
    for (int mi = 0; mi < 4; mi++)
#pragma unroll
        for (int ni = 0; ni < 4; ni++)
#pragma unroll
            for (int q = 0; q < 4; q++) acc[mi][ni][q] = 0.0f;

    // Prologue: A tile (whole K) as one group, then first ST-1 B stages.
#pragma unroll
    for (int i = tid; i < 8 * KT16 * 32; i += 512)
        cp16(&As[i], gA + i);
    CP_COMMIT();
#pragma unroll
    for (int s = 0; s < ST - 1; s++) {
        cp16(&Bs[(s * 16 + (tid >> 5)) * 32 + lane],
             gB + ((size_t)(tid >> 5) * KT16 + s) * 32 + lane);
        CP_COMMIT();
    }

    for (int kt = 0; kt < KT16; kt++) {
        if (kt + ST - 1 < KT16) {
            int st = (kt + ST - 1) % ST, kk = kt + ST - 1;
            cp16(&Bs[(st * 16 + (tid >> 5)) * 32 + lane],
                 gB + ((size_t)(tid >> 5) * KT16 + kk) * 32 + lane);
        }
        CP_COMMIT();
        CP_WAIT(ST - 2);
        __syncthreads();

        const int st = kt % ST;
        uint4 af[4], bf[2];
#pragma unroll
        for (int mi = 0; mi < 4; mi++)
            af[mi] = As[((wM * 4 + mi) * KT16 + kt) * 32 + lane];
#pragma unroll
        for (int p = 0; p < 2; p++)
            bf[p] = Bs[(st * 16 + wN * 2 + p) * 32 + lane];

#pragma unroll
        for (int mi = 0; mi < 4; mi++) {
            unsigned a[4] = { af[mi].x, af[mi].y, af[mi].z, af[mi].w };
#pragma unroll
            for (int ni = 0; ni < 4; ni++) {
                const uint4& q = bf[ni >> 1];
                unsigned b[2];
                if (ni & 1) { b[0] = q.z; b[1] = q.w; }
                else        { b[0] = q.x; b[1] = q.y; }
                mma_f16(acc[mi][ni], a, b);
            }
        }
        __syncthreads();
    }

    // epilogue: add exact DC term, write float2 pairs
    const float inv = 0.0078125f;       // 1/sqrt(N)
    const int rowW = mtile * 128 + wM * 64;
    const int colW = ntile * 256 + wN * 32;
#pragma unroll
    for (int mi = 0; mi < 4; mi++) {
        int r = rowW + mi * 16 + g;
        float d0 = g_dc[r] * inv;
        float d1 = g_dc[r + 8] * inv;
#pragma unroll
        for (int ni = 0; ni < 4; ni++) {
            int c = colW + (ni >> 1) * 16 + (ni & 1) * 8 + 2 * t;
            *(float2*)&out[(size_t)r * NN + c] =
                make_float2(acc[mi][ni][0] + d0, acc[mi][ni][1] + d0);
            *(float2*)&out[(size_t)(r + 8) * NN + c] =
                make_float2(acc[mi][ni][2] + d1, acc[mi][ni][3] + d1);
        }
    }
}

// ---------------------------------------------------------------------------
extern "C" void kernel_launch(void* const* d_in, const int* in_sizes, int n_in,
                              void* d_out, int out_size) {
    const float* x      = (const float*)d_in[0];   // [4096, 2048]
    const float* W_proj = (const float*)d_in[1];   // [129, 2048]
    const float* b_proj = (const float*)d_in[2];   // [129]
    const float* Ws     = (const float*)d_in[3];   // [16384, 64]
    float* out = (float*)d_out;                    // [4096, 16384]

    cudaFuncSetAttribute(gemm2_frag_kernel,
                         cudaFuncAttributeMaxDynamicSharedMemorySize, G2_SMEM);

    prep_kernel<<<BASIS_BLOCKS + ZERO_BLOCKS, 256>>>(Ws);

    dim3 g1(BS_ / 128, IN_DIM_ / 128);             // (32, 16) split-K
    gemm1_mma_kernel<<<g1, 256>>>(x, W_proj);

    finalize_frag_kernel<<<(BS_ / 16) * KT16 / 8, 256>>>(b_proj);

    dim3 g2(BS_ / 128, NN / 256);                  // (32 m, 64 n)
    gemm2_frag_kernel<<<g2, 512, G2_SMEM>>>(out);
}

// round 9
// speedup vs baseline: 4.1402x; 1.1642x over previous
#include <cuda_runtime.h>
#include <cuda_fp16.h>
#include <math.h>

// Problem constants
#define BS_      4096
#define IN_DIM_  2048
#define NN       16384
#define TOTAL_D_ 129      // 1 (dc) + 64 (pairs) + 64 (slack)
#define KPAD     136      // gemm1 accumulator row count
#define KT16     9        // gemm2 k-chunks of 16 (144 padded)

// Scratch (static device globals -- no dynamic allocation allowed)
__device__ float g_hacc[KPAD * BS_];           // [j][b] fp32 gemm1 accumulator
__device__ float g_dc[BS_];                    // exact fp32 h[:,0]
// fp16 fragment-shuffled operands for mma.m16n8k16:
//  g_hF[m16][kt][lane] = {a0,a1,a2,a3} packed half2   (A = h[b][j])
//  g_MF[n16][kt][lane] = {b0lo,b1lo,b0hi,b1hi}        (B = M[n][j])
__device__ uint4 g_hF[(BS_ / 16) * KT16 * 32]; // 1.2 MB
__device__ uint4 g_MF[(NN  / 16) * KT16 * 32]; // 4.7 MB

__device__ __forceinline__ void mma_f16(float* c, const unsigned* a, const unsigned* b) {
    asm volatile(
        "mma.sync.aligned.m16n8k16.row.col.f32.f16.f16.f32 "
        "{%0,%1,%2,%3}, {%4,%5,%6,%7}, {%8,%9}, {%0,%1,%2,%3};\n"
        : "+f"(c[0]), "+f"(c[1]), "+f"(c[2]), "+f"(c[3])
        : "r"(a[0]), "r"(a[1]), "r"(a[2]), "r"(a[3]), "r"(b[0]), "r"(b[1]));
}

__device__ __forceinline__ void cp16(void* smem, const void* gptr) {
    unsigned s = (unsigned)__cvta_generic_to_shared(smem);
    asm volatile("cp.async.cg.shared.global [%0], [%1], 16;" :: "r"(s), "l"(gptr));
}
#define CP_COMMIT() asm volatile("cp.async.commit_group;")
#define CP_WAIT(n)  asm volatile("cp.async.wait_group %0;" :: "n"(n))

// M[n][j] basis value (DC column j==0 excluded; handled exactly in epilogue)
__device__ __forceinline__ float basis_val(int n, int j, const float* __restrict__ Ws) {
    if (j >= 1 && j <= 64) {
        const float s2i = 1.41421356237309515f * 0.0078125f;
        const float w0  = 6.28318530717958647692f / (float)NN;
        int k = (j + 1) >> 1;
        int m = (k * n) & (NN - 1);
        if (m >= NN / 2) m -= NN;            // theta in [-pi, pi)
        float th = (float)m * w0;
        float s, c;
        __sincosf(th, &s, &c);
        return (j & 1) ? s2i * c : s2i * s;
    }
    if (j >= 65 && j < TOTAL_D_) return Ws[n * 64 + (j - 65)];
    return 0.0f;
}

// ---------------------------------------------------------------------------
// Fused kernel 1: blocks [0, 1152)       -> basis fragments (MUFU-heavy)
//                 blocks [1152, 1664)    -> gemm1 (tensor-heavy), overlapped.
// g_hacc is zeroed beforehand by a cudaMemsetAsync node.
// ---------------------------------------------------------------------------
#define BASIS_BLOCKS ((NN / 16) * KT16 / 8)    // 1152
#define G1_BLOCKS    (32 * 16)                 // 512 (32 m-tiles x 16 k-segs)

__global__ __launch_bounds__(256, 2)
void prep_gemm1_kernel(const float* __restrict__ x, const float* __restrict__ W,
                       const float* __restrict__ Ws) {
    __shared__ __half2 Ah[8][136];   // gemm1 x tile  [kpair][m]
    __shared__ __half2 Bh[8][152];   // gemm1 W tile  [kpair][j]

    if (blockIdx.x < BASIS_BLOCKS) {
        // ---- basis fragments ----
        int w = (blockIdx.x * blockDim.x + threadIdx.x) >> 5;
        int lane = threadIdx.x & 31;
        int n16 = w / KT16, kt = w % KT16;
        int g = lane >> 2, t = lane & 3;
        int j0 = 16 * kt + 2 * t;
        unsigned r[4];
#pragma unroll
        for (int nsel = 0; nsel < 2; nsel++) {
            int n = n16 * 16 + nsel * 8 + g;
            __half2 lo = __floats2half2_rn(basis_val(n, j0,     Ws), basis_val(n, j0 + 1, Ws));
            __half2 hi = __floats2half2_rn(basis_val(n, j0 + 8, Ws), basis_val(n, j0 + 9, Ws));
            r[2 * nsel]     = *(unsigned*)&lo;
            r[2 * nsel + 1] = *(unsigned*)&hi;
        }
        g_MF[(size_t)w * 32 + lane] = make_uint4(r[0], r[1], r[2], r[3]);
        return;
    }

    // ---- gemm1: hacc[j][b] += sum_k x[b][k] * W[j][k] (split-K atomics) ----
    const int bid  = blockIdx.x - BASIS_BLOCKS;
    const int rowBase = (bid & 31) * 128;
    const int kSeg    = (bid >> 5) * 128;
    const int tid  = threadIdx.x;
    const int warp = tid >> 5, lane = tid & 31;
    const int wM = warp & 3, wN = warp >> 2;
    const int m0 = wM * 32, n0 = wN * 72;
    const int g = lane >> 2, t = lane & 3;

    float acc[2][9][4];
#pragma unroll
    for (int mi = 0; mi < 2; mi++)
#pragma unroll
        for (int ni = 0; ni < 9; ni++)
#pragma unroll
            for (int q = 0; q < 4; q++) acc[mi][ni][q] = 0.0f;

    for (int kc = 0; kc < 128; kc += 16) {
        const int kBase = kSeg + kc;
#pragma unroll
        for (int i = tid; i < 512; i += 256) {
            int r = i >> 2, kp = (i & 3) << 1;
            float4 v = *(const float4*)&x[(size_t)(rowBase + r) * IN_DIM_ + kBase + 2 * kp];
            Ah[kp][r]     = __floats2half2_rn(v.x, v.y);
            Ah[kp + 1][r] = __floats2half2_rn(v.z, v.w);
        }
        for (int i = tid; i < 576; i += 256) {
            int j = i >> 2, kp = (i & 3) << 1;
            float4 v = make_float4(0.f, 0.f, 0.f, 0.f);
            if (j < TOTAL_D_)
                v = *(const float4*)&W[(size_t)j * IN_DIM_ + kBase + 2 * kp];
            Bh[kp][j]     = __floats2half2_rn(v.x, v.y);
            Bh[kp + 1][j] = __floats2half2_rn(v.z, v.w);
        }
        __syncthreads();

        unsigned a[2][4], b[9][2];
#pragma unroll
        for (int mi = 0; mi < 2; mi++) {
            int r = m0 + mi * 16 + g;
            a[mi][0] = *(unsigned*)&Ah[t][r];
            a[mi][1] = *(unsigned*)&Ah[t][r + 8];
            a[mi][2] = *(unsigned*)&Ah[t + 4][r];
            a[mi][3] = *(unsigned*)&Ah[t + 4][r + 8];
        }
#pragma unroll
        for (int ni = 0; ni < 9; ni++) {
            int c = n0 + ni * 8 + g;
            b[ni][0] = *(unsigned*)&Bh[t][c];
            b[ni][1] = *(unsigned*)&Bh[t + 4][c];
        }
#pragma unroll
        for (int mi = 0; mi < 2; mi++)
#pragma unroll
            for (int ni = 0; ni < 9; ni++)
                mma_f16(acc[mi][ni], a[mi], b[ni]);
        __syncthreads();
    }

#pragma unroll
    for (int mi = 0; mi < 2; mi++) {
        int r = rowBase + m0 + mi * 16 + g;
#pragma unroll
        for (int ni = 0; ni < 9; ni++) {
            int col = n0 + ni * 8 + 2 * t;
            if (col < KPAD) {
                atomicAdd(&g_hacc[(size_t)col * BS_ + r],           acc[mi][ni][0]);
                atomicAdd(&g_hacc[(size_t)(col + 1) * BS_ + r],     acc[mi][ni][1]);
                atomicAdd(&g_hacc[(size_t)col * BS_ + r + 8],       acc[mi][ni][2]);
                atomicAdd(&g_hacc[(size_t)(col + 1) * BS_ + r + 8], acc[mi][ni][3]);
            }
        }
    }
}

// ---------------------------------------------------------------------------
// Finalize h into fp16 A-fragments: add bias, extract exact DC.
// One warp per (m16, kt). lane(g,t): b = m16*16+g (+8), j = 16kt+{2t,2t+1,+8,+9}
// ---------------------------------------------------------------------------
__global__ void finalize_frag_kernel(const float* __restrict__ b_proj) {
    int w = (blockIdx.x * blockDim.x + threadIdx.x) >> 5;
    int lane = threadIdx.x & 31;
    if (w >= (BS_ / 16) * KT16) return;
    int m16 = w / KT16, kt = w % KT16;
    int g = lane >> 2, t = lane & 3;
    int j0 = 16 * kt + 2 * t;

    unsigned r[4];
#pragma unroll
    for (int ksel = 0; ksel < 2; ksel++) {
        int ja = j0 + ksel * 8, jb = ja + 1;
#pragma unroll
        for (int rsel = 0; rsel < 2; rsel++) {
            int b = m16 * 16 + rsel * 8 + g;
            float va = 0.0f, vb = 0.0f;
            if (ja == 0) {
                g_dc[b] = g_hacc[b] + b_proj[0];          // exact fp32 DC
            } else if (ja < TOTAL_D_) {
                va = g_hacc[(size_t)ja * BS_ + b] + b_proj[ja];
            }
            if (jb < TOTAL_D_)
                vb = g_hacc[(size_t)jb * BS_ + b] + b_proj[jb];
            __half2 p = __floats2half2_rn(va, vb);
            r[ksel * 2 + rsel] = *(unsigned*)&p;
        }
    }
    g_hF[(size_t)w * 32 + lane] = make_uint4(r[0], r[1], r[2], r[3]);
}

// ---------------------------------------------------------------------------
// GEMM2 (fp16 MMA): out[b][n] = sum_j h[b][j] * M[n][j] + dc[b]/128
// Block tile 128(m) x 128(n); 256 threads, 8 warps 2(m) x 4(n); warp 64x32.
// A resident (36.9KB) + B 4-stage ring (16KB) = 53KB -> 2 blocks/SM.
// cp.async issued 2 stages ahead -> 2-iteration rewrite slack -> ONE
// __syncthreads per k-iteration.
// ---------------------------------------------------------------------------
#define ST 4
#define G2_SMEM ((8 * KT16 * 32 + ST * 8 * 32) * 16)   // 53248 bytes
__global__ __launch_bounds__(256, 2)
void gemm2_frag_kernel(float* __restrict__ out) {
    extern __shared__ uint4 smem[];
    uint4* As = smem;                  // [m16][kt][lane] = [8][9][32]
    uint4* Bs = smem + 8 * KT16 * 32;  // [st][n16][lane] = [ST][8][32]

    const int ntile = blockIdx.x;      // 0..127
    const int mtile = blockIdx.y;      // 0..31
    const int tid  = threadIdx.x;
    const int warp = tid >> 5, lane = tid & 31;
    const int wM = warp & 1, wN = warp >> 1;     // 2(m) x 4(n)
    const int g = lane >> 2, t = lane & 3;

    const uint4* __restrict__ gA = g_hF + (size_t)mtile * 8 * KT16 * 32;
    const uint4* __restrict__ gB = g_MF + (size_t)ntile * 8 * KT16 * 32;

    const int ln16 = tid >> 5;         // B load: n16 row this thread fills

    float acc[4][4][4];
#pragma unroll
    for (int mi = 0; mi < 4; mi++)
#pragma unroll
        for (int ni = 0; ni < 4; ni++)
#pragma unroll
            for (int q = 0; q < 4; q++) acc[mi][ni][q] = 0.0f;

    // Prologue: whole-K A tile (group 0), then B stages 0 and 1.
#pragma unroll
    for (int i = tid; i < 8 * KT16 * 32; i += 256)
        cp16(&As[i], gA + i);
    CP_COMMIT();
#pragma unroll
    for (int s = 0; s < 2; s++) {
        cp16(&Bs[(s * 8 + ln16) * 32 + lane],
             gB + ((size_t)ln16 * KT16 + s) * 32 + lane);
        CP_COMMIT();
    }

    for (int kt = 0; kt < KT16; kt++) {
        // Issue 2 stages ahead: stage (kt+2)%ST was last read at kt-2;
        // barrier at kt-1 ordered those reads before this write.
        if (kt + 2 < KT16) {
            int st2 = (kt + 2) % ST;
            cp16(&Bs[(st2 * 8 + ln16) * 32 + lane],
                 gB + ((size_t)ln16 * KT16 + kt + 2) * 32 + lane);
        }
        CP_COMMIT();
        CP_WAIT(2);
        __syncthreads();

        const int st = kt % ST;
        uint4 af[4], bf[2];
#pragma unroll
        for (int mi = 0; mi < 4; mi++)
            af[mi] = As[((wM * 4 + mi) * KT16 + kt) * 32 + lane];
#pragma unroll
        for (int p = 0; p < 2; p++)
            bf[p] = Bs[(st * 8 + wN * 2 + p) * 32 + lane];

#pragma unroll
        for (int mi = 0; mi < 4; mi++) {
            unsigned a[4] = { af[mi].x, af[mi].y, af[mi].z, af[mi].w };
#pragma unroll
            for (int ni = 0; ni < 4; ni++) {
                const uint4& q = bf[ni >> 1];
                unsigned b[2];
                if (ni & 1) { b[0] = q.z; b[1] = q.w; }
                else        { b[0] = q.x; b[1] = q.y; }
                mma_f16(acc[mi][ni], a, b);
            }
        }
    }

    // epilogue: add exact DC term, write float2 pairs
    const float inv = 0.0078125f;       // 1/sqrt(N)
    const int rowW = mtile * 128 + wM * 64;
    const int colW = ntile * 128 + wN * 32;
#pragma unroll
    for (int mi = 0; mi < 4; mi++) {
        int r = rowW + mi * 16 + g;
        float d0 = g_dc[r] * inv;
        float d1 = g_dc[r + 8] * inv;
#pragma unroll
        for (int ni = 0; ni < 4; ni++) {
            int c = colW + (ni >> 1) * 16 + (ni & 1) * 8 + 2 * t;
            *(float2*)&out[(size_t)r * NN + c] =
                make_float2(acc[mi][ni][0] + d0, acc[mi][ni][1] + d0);
            *(float2*)&out[(size_t)(r + 8) * NN + c] =
                make_float2(acc[mi][ni][2] + d1, acc[mi][ni][3] + d1);
        }
    }
}

// ---------------------------------------------------------------------------
extern "C" void kernel_launch(void* const* d_in, const int* in_sizes, int n_in,
                              void* d_out, int out_size) {
    const float* x      = (const float*)d_in[0];   // [4096, 2048]
    const float* W_proj = (const float*)d_in[1];   // [129, 2048]
    const float* b_proj = (const float*)d_in[2];   // [129]
    const float* Ws     = (const float*)d_in[3];   // [16384, 64]
    float* out = (float*)d_out;                    // [4096, 16384]

    cudaFuncSetAttribute(gemm2_frag_kernel,
                         cudaFuncAttributeMaxDynamicSharedMemorySize, G2_SMEM);

    // zero the gemm1 accumulator (memset node; no allocation)
    void* haccPtr = nullptr;
    cudaGetSymbolAddress(&haccPtr, g_hacc);
    cudaMemsetAsync(haccPtr, 0, sizeof(float) * KPAD * BS_);

    // basis prep (MUFU-heavy) fused with gemm1 (tensor-heavy)
    prep_gemm1_kernel<<<BASIS_BLOCKS + G1_BLOCKS, 256>>>(x, W_proj, Ws);

    finalize_frag_kernel<<<(BS_ / 16) * KT16 / 8, 256>>>(b_proj);

    dim3 g2(NN / 128, BS_ / 128);                  // (128 n, 32 m)
    gemm2_frag_kernel<<<g2, 256, G2_SMEM>>>(out);
}

// round 10
// speedup vs baseline: 4.2778x; 1.0332x over previous
#include <cuda_runtime.h>
#include <cuda_fp16.h>
#include <math.h>

// Problem constants
#define BS_      4096
#define IN_DIM_  2048
#define NN       16384
#define TOTAL_D_ 129      // 1 (dc) + 64 (pairs) + 64 (slack)
#define KPAD     136      // gemm1 accumulator row count
#define KT16     9        // gemm2 k-chunks of 16 (144 padded)

// Scratch (static device globals -- no dynamic allocation allowed)
__device__ float g_hacc[KPAD * BS_];           // [j][b] fp32 gemm1 accumulator
__device__ float g_dc[BS_];                    // exact fp32 h[:,0]
// fp16 fragment-shuffled operands for mma.m16n8k16:
//  g_hF[m16][kt][lane] = {a0,a1,a2,a3} packed half2   (A = h[b][j])
//  g_MF[n16][kt][lane] = {b0lo,b1lo,b0hi,b1hi}        (B = M[n][j])
__device__ uint4 g_hF[(BS_ / 16) * KT16 * 32]; // 1.2 MB
__device__ uint4 g_MF[(NN  / 16) * KT16 * 32]; // 4.7 MB

__device__ __forceinline__ void mma_f16(float* c, const unsigned* a, const unsigned* b) {
    asm volatile(
        "mma.sync.aligned.m16n8k16.row.col.f32.f16.f16.f32 "
        "{%0,%1,%2,%3}, {%4,%5,%6,%7}, {%8,%9}, {%0,%1,%2,%3};\n"
        : "+f"(c[0]), "+f"(c[1]), "+f"(c[2]), "+f"(c[3])
        : "r"(a[0]), "r"(a[1]), "r"(a[2]), "r"(a[3]), "r"(b[0]), "r"(b[1]));
}

__device__ __forceinline__ void cp16(void* smem, const void* gptr) {
    unsigned s = (unsigned)__cvta_generic_to_shared(smem);
    asm volatile("cp.async.cg.shared.global [%0], [%1], 16;" :: "r"(s), "l"(gptr));
}
#define CP_COMMIT() asm volatile("cp.async.commit_group;")
#define CP_WAIT(n)  asm volatile("cp.async.wait_group %0;" :: "n"(n))

// ---------------------------------------------------------------------------
// Fused kernel 1: blocks [0, 512)     -> gemm1 (tensor-heavy, long pole)
//                 blocks [512, 640)   -> basis fragments via rotation
//                                        recurrence (2 sincosf per thread).
// g_hacc is zeroed beforehand by a cudaMemsetAsync node.
// ---------------------------------------------------------------------------
#define G1_BLOCKS    512                       // 32 m-tiles x 16 k-segs
#define BASIS_BLOCKS (NN / 128)                // 128 (128 n-rows per block)
#define ROWSTRIDE    152                       // halves; 76 words -> conflict-free

__global__ __launch_bounds__(256, 2)
void prep_gemm1_kernel(const float* __restrict__ x, const float* __restrict__ W,
                       const float* __restrict__ Ws) {
    // union: gemm1 tiles (9.2KB) vs basis staging (38.9KB)
    __shared__ __align__(16) char smem_raw[128 * ROWSTRIDE * 2];

    const int tid = threadIdx.x;

    if (blockIdx.x >= G1_BLOCKS) {
        // ---- basis: M[n][j] rows via rotation recurrence ----
        const int blk = blockIdx.x - G1_BLOCKS;
        __half* Sb = (__half*)smem_raw;
        const int nl = tid >> 1, half = tid & 1;
        const int n  = blk * 128 + nl;
        __half* row = Sb + nl * ROWSTRIDE;

        const float s2i = 1.41421356237309515f * 0.0078125f;  // sqrt2/128
        const float w0  = 6.28318530717958647692f / (float)NN;

        // seed: (c,s) = (cos,sin) of k0*theta ; rotor (c1,s1) = theta
        const int k0 = half ? 17 : 1;
        int m0 = (k0 * n) & (NN - 1); if (m0 >= NN / 2) m0 -= NN;
        int m1 = n;                   if (m1 >= NN / 2) m1 -= NN;
        float c, s, c1, s1;
        sincosf((float)m0 * w0, &s,  &c);    // precise seeds: recurrence drift
        sincosf((float)m1 * w0, &s1, &c1);   //   stays below fp16 rounding
#pragma unroll
        for (int i = 0; i < 16; i++) {
            int k = k0 + i;
            row[2 * k - 1] = __float2half_rn(s2i * c);
            row[2 * k]     = __float2half_rn(s2i * s);
            float cn = fmaf(c, c1, -s * s1);
            float sn = fmaf(s, c1,  c * s1);
            c = cn; s = sn;
        }
        // slack columns j = 65+s  (half 0: s 0..31, half 1: s 32..63)
        const float4* wsrow = (const float4*)(Ws + (size_t)n * 64 + half * 32);
#pragma unroll
        for (int q = 0; q < 8; q++) {
            float4 v = wsrow[q];
            int j = 65 + half * 32 + 4 * q;
            row[j]     = __float2half_rn(v.x);
            row[j + 1] = __float2half_rn(v.y);
            row[j + 2] = __float2half_rn(v.z);
            row[j + 3] = __float2half_rn(v.w);
        }
        if (half == 0) {
            row[0] = __float2half_rn(0.0f);          // DC col (exact in epilogue)
        } else {
#pragma unroll
            for (int j = TOTAL_D_; j < 144; j++)     // pad cols 129..143
                row[j] = __float2half_rn(0.0f);
        }
        __syncthreads();

        // re-emit in mma B-fragment layout
        const int warp = tid >> 5, lane = tid & 31;
        const int g = lane >> 2, t = lane & 3;
        const unsigned* SW = (const unsigned*)Sb;    // 32-bit word view
        const int rlo = (warp * 16 + g) * (ROWSTRIDE / 2);
        const int rhi = rlo + 8 * (ROWSTRIDE / 2);
        const int n16 = blk * 8 + warp;
#pragma unroll
        for (int kt = 0; kt < KT16; kt++) {
            int o = kt * 8 + t;
            g_MF[((size_t)n16 * KT16 + kt) * 32 + lane] =
                make_uint4(SW[rlo + o], SW[rlo + o + 4],
                           SW[rhi + o], SW[rhi + o + 4]);
        }
        return;
    }

    // ---- gemm1: hacc[j][b] += sum_k x[b][k] * W[j][k] (split-K atomics) ----
    __half2 (*Ah)[136] = (__half2(*)[136])smem_raw;               // [kpair][m]
    __half2 (*Bh)[152] = (__half2(*)[152])(smem_raw + 8 * 136 * 4); // [kpair][j]

    const int bid  = blockIdx.x;
    const int rowBase = (bid & 31) * 128;
    const int kSeg    = (bid >> 5) * 128;
    const int warp = tid >> 5, lane = tid & 31;
    const int wM = warp & 3, wN = warp >> 2;
    const int m0 = wM * 32, n0 = wN * 72;
    const int g = lane >> 2, t = lane & 3;

    float acc[2][9][4];
#pragma unroll
    for (int mi = 0; mi < 2; mi++)
#pragma unroll
        for (int ni = 0; ni < 9; ni++)
#pragma unroll
            for (int q = 0; q < 4; q++) acc[mi][ni][q] = 0.0f;

    for (int kc = 0; kc < 128; kc += 16) {
        const int kBase = kSeg + kc;
#pragma unroll
        for (int i = tid; i < 512; i += 256) {
            int r = i >> 2, kp = (i & 3) << 1;
            float4 v = *(const float4*)&x[(size_t)(rowBase + r) * IN_DIM_ + kBase + 2 * kp];
            Ah[kp][r]     = __floats2half2_rn(v.x, v.y);
            Ah[kp + 1][r] = __floats2half2_rn(v.z, v.w);
        }
        for (int i = tid; i < 576; i += 256) {
            int j = i >> 2, kp = (i & 3) << 1;
            float4 v = make_float4(0.f, 0.f, 0.f, 0.f);
            if (j < TOTAL_D_)
                v = *(const float4*)&W[(size_t)j * IN_DIM_ + kBase + 2 * kp];
            Bh[kp][j]     = __floats2half2_rn(v.x, v.y);
            Bh[kp + 1][j] = __floats2half2_rn(v.z, v.w);
        }
        __syncthreads();

        unsigned a[2][4], b[9][2];
#pragma unroll
        for (int mi = 0; mi < 2; mi++) {
            int r = m0 + mi * 16 + g;
            a[mi][0] = *(unsigned*)&Ah[t][r];
            a[mi][1] = *(unsigned*)&Ah[t][r + 8];
            a[mi][2] = *(unsigned*)&Ah[t + 4][r];
            a[mi][3] = *(unsigned*)&Ah[t + 4][r + 8];
        }
#pragma unroll
        for (int ni = 0; ni < 9; ni++) {
            int c = n0 + ni * 8 + g;
            b[ni][0] = *(unsigned*)&Bh[t][c];
            b[ni][1] = *(unsigned*)&Bh[t + 4][c];
        }
#pragma unroll
        for (int mi = 0; mi < 2; mi++)
#pragma unroll
            for (int ni = 0; ni < 9; ni++)
                mma_f16(acc[mi][ni], a[mi], b[ni]);
        __syncthreads();
    }

#pragma unroll
    for (int mi = 0; mi < 2; mi++) {
        int r = rowBase + m0 + mi * 16 + g;
#pragma unroll
        for (int ni = 0; ni < 9; ni++) {
            int col = n0 + ni * 8 + 2 * t;
            if (col < KPAD) {
                atomicAdd(&g_hacc[(size_t)col * BS_ + r],           acc[mi][ni][0]);
                atomicAdd(&g_hacc[(size_t)(col + 1) * BS_ + r],     acc[mi][ni][1]);
                atomicAdd(&g_hacc[(size_t)col * BS_ + r + 8],       acc[mi][ni][2]);
                atomicAdd(&g_hacc[(size_t)(col + 1) * BS_ + r + 8], acc[mi][ni][3]);
            }
        }
    }
}

// ---------------------------------------------------------------------------
// Finalize h into fp16 A-fragments: add bias, extract exact DC.
// One warp per (m16, kt). lane(g,t): b = m16*16+g (+8), j = 16kt+{2t,2t+1,+8,+9}
// ---------------------------------------------------------------------------
__global__ void finalize_frag_kernel(const float* __restrict__ b_proj) {
    int w = (blockIdx.x * blockDim.x + threadIdx.x) >> 5;
    int lane = threadIdx.x & 31;
    if (w >= (BS_ / 16) * KT16) return;
    int m16 = w / KT16, kt = w % KT16;
    int g = lane >> 2, t = lane & 3;
    int j0 = 16 * kt + 2 * t;

    unsigned r[4];
#pragma unroll
    for (int ksel = 0; ksel < 2; ksel++) {
        int ja = j0 + ksel * 8, jb = ja + 1;
#pragma unroll
        for (int rsel = 0; rsel < 2; rsel++) {
            int b = m16 * 16 + rsel * 8 + g;
            float va = 0.0f, vb = 0.0f;
            if (ja == 0) {
                g_dc[b] = g_hacc[b] + b_proj[0];          // exact fp32 DC
            } else if (ja < TOTAL_D_) {
                va = g_hacc[(size_t)ja * BS_ + b] + b_proj[ja];
            }
            if (jb < TOTAL_D_)
                vb = g_hacc[(size_t)jb * BS_ + b] + b_proj[jb];
            __half2 p = __floats2half2_rn(va, vb);
            r[ksel * 2 + rsel] = *(unsigned*)&p;
        }
    }
    g_hF[(size_t)w * 32 + lane] = make_uint4(r[0], r[1], r[2], r[3]);
}

// ---------------------------------------------------------------------------
// GEMM2 (fp16 MMA): out[b][n] = sum_j h[b][j] * M[n][j] + dc[b]/128
// Block tile 128(m) x 128(n); 256 threads, 8 warps 2(m) x 4(n); warp 64x32.
// A resident (36.9KB) + B 4-stage ring (16KB) = 53KB -> 2 blocks/SM.
// cp.async issued 2 stages ahead -> ONE __syncthreads per k-iteration.
// ---------------------------------------------------------------------------
#define ST 4
#define G2_SMEM ((8 * KT16 * 32 + ST * 8 * 32) * 16)   // 53248 bytes
__global__ __launch_bounds__(256, 2)
void gemm2_frag_kernel(float* __restrict__ out) {
    extern __shared__ uint4 smem[];
    uint4* As = smem;                  // [m16][kt][lane] = [8][9][32]
    uint4* Bs = smem + 8 * KT16 * 32;  // [st][n16][lane] = [ST][8][32]

    const int ntile = blockIdx.x;      // 0..127
    const int mtile = blockIdx.y;      // 0..31
    const int tid  = threadIdx.x;
    const int warp = tid >> 5, lane = tid & 31;
    const int wM = warp & 1, wN = warp >> 1;     // 2(m) x 4(n)
    const int g = lane >> 2, t = lane & 3;

    const uint4* __restrict__ gA = g_hF + (size_t)mtile * 8 * KT16 * 32;
    const uint4* __restrict__ gB = g_MF + (size_t)ntile * 8 * KT16 * 32;

    const int ln16 = tid >> 5;         // B load: n16 row this thread fills

    float acc[4][4][4];
#pragma unroll
    for (int mi = 0; mi < 4; mi++)
#pragma unroll
        for (int ni = 0; ni < 4; ni++)
#pragma unroll
            for (int q = 0; q < 4; q++) acc[mi][ni][q] = 0.0f;

    // Prologue: whole-K A tile (group 0), then B stages 0 and 1.
#pragma unroll
    for (int i = tid; i < 8 * KT16 * 32; i += 256)
        cp16(&As[i], gA + i);
    CP_COMMIT();
#pragma unroll
    for (int s = 0; s < 2; s++) {
        cp16(&Bs[(s * 8 + ln16) * 32 + lane],
             gB + ((size_t)ln16 * KT16 + s) * 32 + lane);
        CP_COMMIT();
    }

    for (int kt = 0; kt < KT16; kt++) {
        if (kt + 2 < KT16) {
            int st2 = (kt + 2) % ST;
            cp16(&Bs[(st2 * 8 + ln16) * 32 + lane],
                 gB + ((size_t)ln16 * KT16 + kt + 2) * 32 + lane);
        }
        CP_COMMIT();
        CP_WAIT(2);
        __syncthreads();

        const int st = kt % ST;
        uint4 af[4], bf[2];
#pragma unroll
        for (int mi = 0; mi < 4; mi++)
            af[mi] = As[((wM * 4 + mi) * KT16 + kt) * 32 + lane];
#pragma unroll
        for (int p = 0; p < 2; p++)
            bf[p] = Bs[(st * 8 + wN * 2 + p) * 32 + lane];

#pragma unroll
        for (int mi = 0; mi < 4; mi++) {
            unsigned a[4] = { af[mi].x, af[mi].y, af[mi].z, af[mi].w };
#pragma unroll
            for (int ni = 0; ni < 4; ni++) {
                const uint4& q = bf[ni >> 1];
                unsigned b[2];
                if (ni & 1) { b[0] = q.z; b[1] = q.w; }
                else        { b[0] = q.x; b[1] = q.y; }
                mma_f16(acc[mi][ni], a, b);
            }
        }
    }

    // epilogue: add exact DC term, write float2 pairs
    const float inv = 0.0078125f;       // 1/sqrt(N)
    const int rowW = mtile * 128 + wM * 64;
    const int colW = ntile * 128 + wN * 32;
#pragma unroll
    for (int mi = 0; mi < 4; mi++) {
        int r = rowW + mi * 16 + g;
        float d0 = g_dc[r] * inv;
        float d1 = g_dc[r + 8] * inv;
#pragma unroll
        for (int ni = 0; ni < 4; ni++) {
            int c = colW + (ni >> 1) * 16 + (ni & 1) * 8 + 2 * t;
            *(float2*)&out[(size_t)r * NN + c] =
                make_float2(acc[mi][ni][0] + d0, acc[mi][ni][1] + d0);
            *(float2*)&out[(size_t)(r + 8) * NN + c] =
                make_float2(acc[mi][ni][2] + d1, acc[mi][ni][3] + d1);
        }
    }
}

// ---------------------------------------------------------------------------
extern "C" void kernel_launch(void* const* d_in, const int* in_sizes, int n_in,
                              void* d_out, int out_size) {
    const float* x      = (const float*)d_in[0];   // [4096, 2048]
    const float* W_proj = (const float*)d_in[1];   // [129, 2048]
    const float* b_proj = (const float*)d_in[2];   // [129]
    const float* Ws     = (const float*)d_in[3];   // [16384, 64]
    float* out = (float*)d_out;                    // [4096, 16384]

    cudaFuncSetAttribute(gemm2_frag_kernel,
                         cudaFuncAttributeMaxDynamicSharedMemorySize, G2_SMEM);

    // zero the gemm1 accumulator (memset node; no allocation)
    void* haccPtr = nullptr;
    cudaGetSymbolAddress(&haccPtr, g_hacc);
    cudaMemsetAsync(haccPtr, 0, sizeof(float) * KPAD * BS_);

    // gemm1 (tensor-heavy, blocks first) fused with basis prep (recurrence)
    prep_gemm1_kernel<<<G1_BLOCKS + BASIS_BLOCKS, 256>>>(x, W_proj, Ws);

    finalize_frag_kernel<<<(BS_ / 16) * KT16 / 8, 256>>>(b_proj);

    dim3 g2(NN / 128, BS_ / 128);                  // (128 n, 32 m)
    gemm2_frag_kernel<<<g2, 256, G2_SMEM>>>(out);
}

// round 11
// speedup vs baseline: 4.6764x; 1.0932x over previous
#include <cuda_runtime.h>
#include <cuda_fp16.h>
#include <math.h>

// Problem constants
#define BS_      4096
#define IN_DIM_  2048
#define NN       16384
#define TOTAL_D_ 129      // 1 (dc) + 64 (pairs) + 64 (slack)
#define KPAD     136      // gemm1 accumulator row count
#define KT16     9        // gemm2 k-chunks of 16 (144 padded)

// Scratch (static device globals -- no dynamic allocation allowed)
__device__ float g_hacc[KPAD * BS_];           // [j][b] fp32 gemm1 accumulator
__device__ float g_dc[BS_];                    // exact fp32 h[:,0]
// fp16 fragment-shuffled operands for mma.m16n8k16:
//  g_hF[m16][kt][lane] = {a0,a1,a2,a3} packed half2   (A = h[b][j])
//  g_MF[n16][kt][lane] = {b0lo,b1lo,b0hi,b1hi}        (B = M[n][j])
__device__ uint4 g_hF[(BS_ / 16) * KT16 * 32]; // 1.2 MB
__device__ uint4 g_MF[(NN  / 16) * KT16 * 32]; // 4.7 MB

__device__ __forceinline__ void mma_f16(float* c, const unsigned* a, const unsigned* b) {
    asm volatile(
        "mma.sync.aligned.m16n8k16.row.col.f32.f16.f16.f32 "
        "{%0,%1,%2,%3}, {%4,%5,%6,%7}, {%8,%9}, {%0,%1,%2,%3};\n"
        : "+f"(c[0]), "+f"(c[1]), "+f"(c[2]), "+f"(c[3])
        : "r"(a[0]), "r"(a[1]), "r"(a[2]), "r"(a[3]), "r"(b[0]), "r"(b[1]));
}

__device__ __forceinline__ void cp16(void* smem, const void* gptr) {
    unsigned s = (unsigned)__cvta_generic_to_shared(smem);
    asm volatile("cp.async.cg.shared.global [%0], [%1], 16;" :: "r"(s), "l"(gptr));
}
#define CP_COMMIT() asm volatile("cp.async.commit_group;")
#define CP_WAIT(n)  asm volatile("cp.async.wait_group %0;" :: "n"(n))

__device__ __forceinline__ unsigned packh2(float lo, float hi) {
    __half2 p = __floats2half2_rn(lo, hi);
    return *(unsigned*)&p;
}

// ---------------------------------------------------------------------------
// Fused kernel 1: blocks [0, 512)     -> gemm1 (cp.async pipelined, fp16 MMA)
//                 blocks [512, 640)   -> basis fragments (rotation recurrence)
// g_hacc is zeroed beforehand by a cudaMemsetAsync node.
// ---------------------------------------------------------------------------
#define G1_BLOCKS    512                       // 32 m-tiles x 16 k-segs
#define BASIS_BLOCKS (NN / 128)                // 128 (128 n-rows per block)
#define ROWSTRIDE    152                       // basis staging stride (halves)

// gemm1 pipeline geometry: raw f32 tiles, row-major [row][k16], stride 20 words
#define RS       20                            // words per row (16B aligned)
#define A_WORDS  (128 * RS)                    // 2560
#define B_WORDS  (144 * RS)                    // 2880 (rows 129..143 stay zero)
#define STG_W    (A_WORDS + B_WORDS)           // 5440 words / stage
#define G1ST     4
#define PG1_SMEM (G1ST * STG_W * 4)            // 87040 bytes

__global__ __launch_bounds__(256, 2)
void prep_gemm1_kernel(const float* __restrict__ x, const float* __restrict__ W,
                       const float* __restrict__ Ws) {
    extern __shared__ __align__(16) float smf[];   // gemm1 ring / basis staging

    const int tid = threadIdx.x;

    if (blockIdx.x >= G1_BLOCKS) {
        // ---- basis: M[n][j] rows via rotation recurrence ----
        const int blk = blockIdx.x - G1_BLOCKS;
        __half* Sb = (__half*)smf;
        const int nl = tid >> 1, half = tid & 1;
        const int n  = blk * 128 + nl;
        __half* row = Sb + nl * ROWSTRIDE;

        const float s2i = 1.41421356237309515f * 0.0078125f;  // sqrt2/128
        const float w0  = 6.28318530717958647692f / (float)NN;

        const int k0 = half ? 17 : 1;
        int m0 = (k0 * n) & (NN - 1); if (m0 >= NN / 2) m0 -= NN;
        int m1 = n;                   if (m1 >= NN / 2) m1 -= NN;
        float c, s, c1, s1;
        sincosf((float)m0 * w0, &s,  &c);    // precise seeds: drift < fp16 ulp
        sincosf((float)m1 * w0, &s1, &c1);
#pragma unroll
        for (int i = 0; i < 16; i++) {
            int k = k0 + i;
            row[2 * k - 1] = __float2half_rn(s2i * c);
            row[2 * k]     = __float2half_rn(s2i * s);
            float cn = fmaf(c, c1, -s * s1);
            float sn = fmaf(s, c1,  c * s1);
            c = cn; s = sn;
        }
        const float4* wsrow = (const float4*)(Ws + (size_t)n * 64 + half * 32);
#pragma unroll
        for (int q = 0; q < 8; q++) {
            float4 v = wsrow[q];
            int j = 65 + half * 32 + 4 * q;
            row[j]     = __float2half_rn(v.x);
            row[j + 1] = __float2half_rn(v.y);
            row[j + 2] = __float2half_rn(v.z);
            row[j + 3] = __float2half_rn(v.w);
        }
        if (half == 0) {
            row[0] = __float2half_rn(0.0f);          // DC col (exact in epilogue)
        } else {
#pragma unroll
            for (int j = TOTAL_D_; j < 144; j++)     // pad cols 129..143
                row[j] = __float2half_rn(0.0f);
        }
        __syncthreads();

        // re-emit in mma B-fragment layout
        const int warp = tid >> 5, lane = tid & 31;
        const int g = lane >> 2, t = lane & 3;
        const unsigned* SW = (const unsigned*)Sb;
        const int rlo = (warp * 16 + g) * (ROWSTRIDE / 2);
        const int rhi = rlo + 8 * (ROWSTRIDE / 2);
        const int n16 = blk * 8 + warp;
#pragma unroll
        for (int kt = 0; kt < KT16; kt++) {
            int o = kt * 8 + t;
            g_MF[((size_t)n16 * KT16 + kt) * 32 + lane] =
                make_uint4(SW[rlo + o], SW[rlo + o + 4],
                           SW[rhi + o], SW[rhi + o + 4]);
        }
        return;
    }

    // ---- gemm1: hacc[j][b] += sum_k x[b][k] * W[j][k] (split-K atomics) ----
    const int bid  = blockIdx.x;
    const int rowBase = (bid & 31) * 128;
    const int kSeg    = (bid >> 5) * 128;
    const int warp = tid >> 5, lane = tid & 31;
    const int wM = warp & 3, wN = warp >> 2;
    const int m0 = wM * 32, n0 = wN * 72;
    const int g = lane >> 2, t = lane & 3;

    // zero W-tile pad rows (129..143) in every stage; cp.async never writes them
#pragma unroll
    for (int st = 0; st < G1ST; st++)
        for (int i = tid; i < 15 * RS; i += 256)
            smf[st * STG_W + A_WORDS + 129 * RS + i] = 0.0f;
    // (ordered before first reads by the iteration-0 barrier)

    float acc[2][9][4];
#pragma unroll
    for (int mi = 0; mi < 2; mi++)
#pragma unroll
        for (int ni = 0; ni < 9; ni++)
#pragma unroll
            for (int q = 0; q < 4; q++) acc[mi][ni][q] = 0.0f;

    // stage fill: A = x tile 128x16 (512 cp16), B = W tile 129x16 (516 cp16)
    auto load_stage = [&](int st, int chunk) {
        float* Sa = smf + st * STG_W;
        float* Sb = smf + st * STG_W + A_WORDS;
        const int kBase = kSeg + chunk * 16;
#pragma unroll
        for (int i = tid; i < 512; i += 256) {
            int r = i >> 2, q = i & 3;
            cp16(&Sa[r * RS + 4 * q],
                 &x[(size_t)(rowBase + r) * IN_DIM_ + kBase + 4 * q]);
        }
        for (int i = tid; i < 516; i += 256) {
            int j = i >> 2, q = i & 3;
            cp16(&Sb[j * RS + 4 * q],
                 &W[(size_t)j * IN_DIM_ + kBase + 4 * q]);
        }
    };

    // prologue: stages 0,1
#pragma unroll
    for (int s = 0; s < 2; s++) { load_stage(s, s); CP_COMMIT(); }

    for (int kc = 0; kc < 8; kc++) {
        if (kc + 2 < 8) load_stage((kc + 2) % G1ST, kc + 2);
        CP_COMMIT();
        CP_WAIT(2);
        __syncthreads();

        const float* Sa = smf + (kc % G1ST) * STG_W;
        const float* Sb = smf + (kc % G1ST) * STG_W + A_WORDS;

        unsigned a[2][4], b[9][2];
#pragma unroll
        for (int mi = 0; mi < 2; mi++) {
            int r = m0 + mi * 16 + g;
            float2 v0 = *(const float2*)&Sa[(r)     * RS + 2 * t];
            float2 v1 = *(const float2*)&Sa[(r + 8) * RS + 2 * t];
            float2 v2 = *(const float2*)&Sa[(r)     * RS + 2 * t + 8];
            float2 v3 = *(const float2*)&Sa[(r + 8) * RS + 2 * t + 8];
            a[mi][0] = packh2(v0.x, v0.y);
            a[mi][1] = packh2(v1.x, v1.y);
            a[mi][2] = packh2(v2.x, v2.y);
            a[mi][3] = packh2(v3.x, v3.y);
        }
#pragma unroll
        for (int ni = 0; ni < 9; ni++) {
            int c = n0 + ni * 8 + g;
            float2 v0 = *(const float2*)&Sb[c * RS + 2 * t];
            float2 v1 = *(const float2*)&Sb[c * RS + 2 * t + 8];
            b[ni][0] = packh2(v0.x, v0.y);
            b[ni][1] = packh2(v1.x, v1.y);
        }
#pragma unroll
        for (int mi = 0; mi < 2; mi++)
#pragma unroll
            for (int ni = 0; ni < 9; ni++)
                mma_f16(acc[mi][ni], a[mi], b[ni]);
    }

#pragma unroll
    for (int mi = 0; mi < 2; mi++) {
        int r = rowBase + m0 + mi * 16 + g;
#pragma unroll
        for (int ni = 0; ni < 9; ni++) {
            int col = n0 + ni * 8 + 2 * t;
            if (col < KPAD) {
                atomicAdd(&g_hacc[(size_t)col * BS_ + r],           acc[mi][ni][0]);
                atomicAdd(&g_hacc[(size_t)(col + 1) * BS_ + r],     acc[mi][ni][1]);
                atomicAdd(&g_hacc[(size_t)col * BS_ + r + 8],       acc[mi][ni][2]);
                atomicAdd(&g_hacc[(size_t)(col + 1) * BS_ + r + 8], acc[mi][ni][3]);
            }
        }
    }
}

// ---------------------------------------------------------------------------
// Finalize h into fp16 A-fragments: add bias, extract exact DC.
// One warp per (m16, kt). lane(g,t): b = m16*16+g (+8), j = 16kt+{2t,2t+1,+8,+9}
// ---------------------------------------------------------------------------
__global__ void finalize_frag_kernel(const float* __restrict__ b_proj) {
    int w = (blockIdx.x * blockDim.x + threadIdx.x) >> 5;
    int lane = threadIdx.x & 31;
    if (w >= (BS_ / 16) * KT16) return;
    int m16 = w / KT16, kt = w % KT16;
    int g = lane >> 2, t = lane & 3;
    int j0 = 16 * kt + 2 * t;

    unsigned r[4];
#pragma unroll
    for (int ksel = 0; ksel < 2; ksel++) {
        int ja = j0 + ksel * 8, jb = ja + 1;
#pragma unroll
        for (int rsel = 0; rsel < 2; rsel++) {
            int b = m16 * 16 + rsel * 8 + g;
            float va = 0.0f, vb = 0.0f;
            if (ja == 0) {
                g_dc[b] = g_hacc[b] + b_proj[0];          // exact fp32 DC
            } else if (ja < TOTAL_D_) {
                va = g_hacc[(size_t)ja * BS_ + b] + b_proj[ja];
            }
            if (jb < TOTAL_D_)
                vb = g_hacc[(size_t)jb * BS_ + b] + b_proj[jb];
            r[ksel * 2 + rsel] = packh2(va, vb);
        }
    }
    g_hF[(size_t)w * 32 + lane] = make_uint4(r[0], r[1], r[2], r[3]);
}

// ---------------------------------------------------------------------------
// GEMM2 (fp16 MMA): out[b][n] = sum_j h[b][j] * M[n][j] + dc[b]/128
// Block tile 128(m) x 128(n); 256 threads, 8 warps 2(m) x 4(n); warp 64x32.
// A resident (36.9KB) + B 4-stage ring (16KB) = 53KB -> 2 blocks/SM.
// cp.async issued 2 stages ahead -> ONE __syncthreads per k-iteration.
// ---------------------------------------------------------------------------
#define ST 4
#define G2_SMEM ((8 * KT16 * 32 + ST * 8 * 32) * 16)   // 53248 bytes
__global__ __launch_bounds__(256, 2)
void gemm2_frag_kernel(float* __restrict__ out) {
    extern __shared__ uint4 smem[];
    uint4* As = smem;                  // [m16][kt][lane] = [8][9][32]
    uint4* Bs = smem + 8 * KT16 * 32;  // [st][n16][lane] = [ST][8][32]

    const int ntile = blockIdx.x;      // 0..127
    const int mtile = blockIdx.y;      // 0..31
    const int tid  = threadIdx.x;
    const int warp = tid >> 5, lane = tid & 31;
    const int wM = warp & 1, wN = warp >> 1;     // 2(m) x 4(n)
    const int g = lane >> 2, t = lane & 3;

    const uint4* __restrict__ gA = g_hF + (size_t)mtile * 8 * KT16 * 32;
    const uint4* __restrict__ gB = g_MF + (size_t)ntile * 8 * KT16 * 32;

    const int ln16 = tid >> 5;

    float acc[4][4][4];
#pragma unroll
    for (int mi = 0; mi < 4; mi++)
#pragma unroll
        for (int ni = 0; ni < 4; ni++)
#pragma unroll
            for (int q = 0; q < 4; q++) acc[mi][ni][q] = 0.0f;

#pragma unroll
    for (int i = tid; i < 8 * KT16 * 32; i += 256)
        cp16(&As[i], gA + i);
    CP_COMMIT();
#pragma unroll
    for (int s = 0; s < 2; s++) {
        cp16(&Bs[(s * 8 + ln16) * 32 + lane],
             gB + ((size_t)ln16 * KT16 + s) * 32 + lane);
        CP_COMMIT();
    }

    for (int kt = 0; kt < KT16; kt++) {
        if (kt + 2 < KT16) {
            int st2 = (kt + 2) % ST;
            cp16(&Bs[(st2 * 8 + ln16) * 32 + lane],
                 gB + ((size_t)ln16 * KT16 + kt + 2) * 32 + lane);
        }
        CP_COMMIT();
        CP_WAIT(2);
        __syncthreads();

        const int st = kt % ST;
        uint4 af[4], bf[2];
#pragma unroll
        for (int mi = 0; mi < 4; mi++)
            af[mi] = As[((wM * 4 + mi) * KT16 + kt) * 32 + lane];
#pragma unroll
        for (int p = 0; p < 2; p++)
            bf[p] = Bs[(st * 8 + wN * 2 + p) * 32 + lane];

#pragma unroll
        for (int mi = 0; mi < 4; mi++) {
            unsigned a[4] = { af[mi].x, af[mi].y, af[mi].z, af[mi].w };
#pragma unroll
            for (int ni = 0; ni < 4; ni++) {
                const uint4& q = bf[ni >> 1];
                unsigned b[2];
                if (ni & 1) { b[0] = q.z; b[1] = q.w; }
                else        { b[0] = q.x; b[1] = q.y; }
                mma_f16(acc[mi][ni], a, b);
            }
        }
    }

    const float inv = 0.0078125f;       // 1/sqrt(N)
    const int rowW = mtile * 128 + wM * 64;
    const int colW = ntile * 128 + wN * 32;
#pragma unroll
    for (int mi = 0; mi < 4; mi++) {
        int r = rowW + mi * 16 + g;
        float d0 = g_dc[r] * inv;
        float d1 = g_dc[r + 8] * inv;
#pragma unroll
        for (int ni = 0; ni < 4; ni++) {
            int c = colW + (ni >> 1) * 16 + (ni & 1) * 8 + 2 * t;
            *(float2*)&out[(size_t)r * NN + c] =
                make_float2(acc[mi][ni][0] + d0, acc[mi][ni][1] + d0);
            *(float2*)&out[(size_t)(r + 8) * NN + c] =
                make_float2(acc[mi][ni][2] + d1, acc[mi][ni][3] + d1);
        }
    }
}

// ---------------------------------------------------------------------------
extern "C" void kernel_launch(void* const* d_in, const int* in_sizes, int n_in,
                              void* d_out, int out_size) {
    const float* x      = (const float*)d_in[0];   // [4096, 2048]
    const float* W_proj = (const float*)d_in[1];   // [129, 2048]
    const float* b_proj = (const float*)d_in[2];   // [129]
    const float* Ws     = (const float*)d_in[3];   // [16384, 64]
    float* out = (float*)d_out;                    // [4096, 16384]

    cudaFuncSetAttribute(prep_gemm1_kernel,
                         cudaFuncAttributeMaxDynamicSharedMemorySize, PG1_SMEM);
    cudaFuncSetAttribute(gemm2_frag_kernel,
                         cudaFuncAttributeMaxDynamicSharedMemorySize, G2_SMEM);

    // zero the gemm1 accumulator (memset node; no allocation)
    void* haccPtr = nullptr;
    cudaGetSymbolAddress(&haccPtr, g_hacc);
    cudaMemsetAsync(haccPtr, 0, sizeof(float) * KPAD * BS_);

    // gemm1 (cp.async pipelined, blocks first) fused with basis prep
    prep_gemm1_kernel<<<G1_BLOCKS + BASIS_BLOCKS, 256, PG1_SMEM>>>(x, W_proj, Ws);

    finalize_frag_kernel<<<(BS_ / 16) * KT16 / 8, 256>>>(b_proj);

    dim3 g2(NN / 128, BS_ / 128);                  // (128 n, 32 m)
    gemm2_frag_kernel<<<g2, 256, G2_SMEM>>>(out);
}